// round 3
// baseline (speedup 1.0000x reference)
#include <cuda_runtime.h>
#include <cuda_bf16.h>
#include <cstddef>

#define Nn   100000
#define Ed   1600000
#define INC  128
#define HC   256
#define LC   64
#define EPSB 1e-5f

// ------------------------- scratch (device globals, no allocation) ----------
__device__ float g_bufA[(size_t)Nn * HC];
__device__ float g_bufB[(size_t)Nn * HC];
__device__ float g_bufC[(size_t)Nn * HC];
__device__ float g_zbuf[(size_t)Nn * LC];
__device__ float g_dinv[Nn];
__device__ int   g_cnt[Nn];
__device__ int   g_rowstart[Nn + 1];
__device__ int   g_wr[Nn];
__device__ int   g_col[Ed];
__device__ float g_sum[HC];
__device__ float g_sumsq[HC];
__device__ float g_scale[HC];
__device__ float g_shift[HC];
__device__ int   g_is32;   // 1 if edge_index is int32 on device, 0 if int64

// ------------------------- edge dtype detection -----------------------------
// Sample 512 entries (256 from the src region start, 256 from the dst region
// start under the int64 interpretation). Genuine int64 indices are all in
// [0, Nn). If the harness materialized int64 as int32, fused pairs are almost
// surely out of range for at least one sample -> flag int32.
__global__ void k_detect(const long long* __restrict__ ei64) {
    __shared__ int s_bad;
    if (threadIdx.x == 0) s_bad = 0;
    __syncthreads();
    long long v0 = ei64[threadIdx.x];
    long long v1 = ei64[(size_t)Ed + threadIdx.x];
    if (v0 < 0 || v0 >= (long long)Nn || v1 < 0 || v1 >= (long long)Nn)
        atomicOr(&s_bad, 1);
    __syncthreads();
    if (threadIdx.x == 0) g_is32 = s_bad ? 1 : 0;
}

__device__ __forceinline__ int edge_at(const void* ei, int is32, size_t pos) {
    // pos indexes the logical [2, Ed] int array (row-major: src row then dst row)
    if (is32) return ((const int*)ei)[pos];
    return (int)((const long long*)ei)[pos];
}

// ------------------------- small utility kernels ----------------------------
__global__ void k_zero_int(int* p, int n) {
    int i = blockIdx.x * blockDim.x + threadIdx.x;
    if (i < n) p[i] = 0;
}

__global__ void k_hist(const void* __restrict__ ei, int* __restrict__ cnt) {
    int e = blockIdx.x * blockDim.x + threadIdx.x;
    if (e >= Ed) return;
    int is32 = g_is32;
    int dst = edge_at(ei, is32, (size_t)Ed + e);
    if ((unsigned)dst < (unsigned)Nn) atomicAdd(&cnt[dst], 1);
}

__global__ void k_dinv(const int* __restrict__ cnt, float* __restrict__ dinv) {
    int i = blockIdx.x * blockDim.x + threadIdx.x;
    if (i < Nn) dinv[i] = rsqrtf((float)(cnt[i] + 1));
}

// single-block exclusive scan over Nn counts -> rowstart, wr
__global__ void __launch_bounds__(1024) k_scan(const int* __restrict__ cnt,
                                               int* __restrict__ rowstart,
                                               int* __restrict__ wr, int n) {
    __shared__ int sh[1024];
    __shared__ int s_carry;
    int tid = threadIdx.x;
    if (tid == 0) s_carry = 0;
    __syncthreads();
    for (int base = 0; base < n; base += 1024) {
        int i = base + tid;
        int v = (i < n) ? cnt[i] : 0;
        sh[tid] = v;
        __syncthreads();
        for (int off = 1; off < 1024; off <<= 1) {
            int t = (tid >= off) ? sh[tid - off] : 0;
            __syncthreads();
            sh[tid] += t;
            __syncthreads();
        }
        int incl = sh[tid];
        int excl = incl - v;
        int carry = s_carry;
        if (i < n) {
            rowstart[i] = carry + excl;
            wr[i]       = carry + excl;
        }
        __syncthreads();
        if (tid == 1023) s_carry = carry + incl;
        __syncthreads();
    }
    if (tid == 0) rowstart[n] = (s_carry <= Ed) ? s_carry : Ed;
}

__global__ void k_scatter(const void* __restrict__ ei,
                          int* __restrict__ wr, int* __restrict__ col) {
    int e = blockIdx.x * blockDim.x + threadIdx.x;
    if (e >= Ed) return;
    int is32 = g_is32;
    int src = edge_at(ei, is32, (size_t)e);
    int dst = edge_at(ei, is32, (size_t)Ed + e);
    if ((unsigned)dst >= (unsigned)Nn || (unsigned)src >= (unsigned)Nn) return;
    int pos = atomicAdd(&wr[dst], 1);
    if ((unsigned)pos < (unsigned)Ed) col[pos] = src;
}

// ------------------------- aggregation (one warp per node) ------------------
// out[i] = dinv[i]^2 * h[i] + sum_{j in in(i)} dinv[i]*dinv[src_j] * h[src_j] (+bias)
template <int H>
__global__ void __launch_bounds__(256) k_agg(const float* __restrict__ h,
                                             const int* __restrict__ rowstart,
                                             const int* __restrict__ col,
                                             const float* __restrict__ dinv,
                                             const float* __restrict__ bias,
                                             float* __restrict__ out) {
    int warp = (blockIdx.x * blockDim.x + threadIdx.x) >> 5;
    int lane = threadIdx.x & 31;
    if (warp >= Nn) return;

    float di = dinv[warp];
    int jbeg = rowstart[warp];
    int jend = rowstart[warp + 1];

    if (H == 256) {
        const float4* h4 = (const float4*)h;
        float4* o4 = (float4*)out;
        int f0 = lane;       // float4 index 0..31
        int f1 = lane + 32;  // float4 index 32..63
        float cs = di * di;
        float4 x0 = h4[(size_t)warp * 64 + f0];
        float4 x1 = h4[(size_t)warp * 64 + f1];
        float4 a0 = make_float4(cs * x0.x, cs * x0.y, cs * x0.z, cs * x0.w);
        float4 a1 = make_float4(cs * x1.x, cs * x1.y, cs * x1.z, cs * x1.w);
        for (int j = jbeg; j < jend; ++j) {
            int s = col[j];
            float c = di * dinv[s];
            float4 y0 = h4[(size_t)s * 64 + f0];
            float4 y1 = h4[(size_t)s * 64 + f1];
            a0.x += c * y0.x; a0.y += c * y0.y; a0.z += c * y0.z; a0.w += c * y0.w;
            a1.x += c * y1.x; a1.y += c * y1.y; a1.z += c * y1.z; a1.w += c * y1.w;
        }
        o4[(size_t)warp * 64 + f0] = a0;
        o4[(size_t)warp * 64 + f1] = a1;
    } else {  // H == 64
        const float2* h2 = (const float2*)h;
        float2* o2 = (float2*)out;
        int f = lane;  // float2 index 0..31
        float cs = di * di;
        float2 x = h2[(size_t)warp * 32 + f];
        float2 a = make_float2(cs * x.x, cs * x.y);
        for (int j = jbeg; j < jend; ++j) {
            int s = col[j];
            float c = di * dinv[s];
            float2 y = h2[(size_t)s * 32 + f];
            a.x += c * y.x;
            a.y += c * y.y;
        }
        if (bias) {
            float2 b = *(const float2*)(bias + f * 2);
            a.x += b.x;
            a.y += b.y;
        }
        o2[(size_t)warp * 32 + f] = a;
    }
}

// ------------------------- BatchNorm helpers (width fixed at HC=256) --------
__global__ void k_bn_zero(float* sum, float* sumsq) {
    int c = threadIdx.x;
    sum[c] = 0.f;
    sumsq[c] = 0.f;
}

__global__ void __launch_bounds__(256) k_bn_stats(const float* __restrict__ x,
                                                  float* __restrict__ sum,
                                                  float* __restrict__ sumsq) {
    int col = threadIdx.x;
    int r0 = blockIdx.x * 256;
    int rend = min(r0 + 256, Nn);
    float s = 0.f, ss = 0.f;
    for (int r = r0; r < rend; ++r) {
        float v = x[(size_t)r * HC + col];
        s += v;
        ss += v * v;
    }
    atomicAdd(&sum[col], s);
    atomicAdd(&sumsq[col], ss);
}

__global__ void k_bn_finalize(const float* __restrict__ sum,
                              const float* __restrict__ sumsq,
                              const float* __restrict__ gamma,
                              const float* __restrict__ beta,
                              float* __restrict__ scale,
                              float* __restrict__ shift) {
    int c = threadIdx.x;
    float invM = 1.f / (float)Nn;
    float m = sum[c] * invM;
    float v = fmaxf(sumsq[c] * invM - m * m, 0.f);
    float sc = gamma[c] * rsqrtf(v + EPSB);
    scale[c] = sc;
    shift[c] = beta[c] - m * sc;
}

// y = relu(x*scale + shift), width HC
__global__ void __launch_bounds__(256) k_bn_apply(const float* __restrict__ x,
                                                  const float* __restrict__ scale,
                                                  const float* __restrict__ shift,
                                                  float* __restrict__ y) {
    size_t idx = (size_t)blockIdx.x * blockDim.x + threadIdx.x;
    size_t n4 = (size_t)Nn * HC / 4;
    if (idx >= n4) return;
    int c = ((int)(idx & 63)) * 4;  // 64 float4 per row
    float4 v = ((const float4*)x)[idx];
    float4 sc = *(const float4*)(scale + c);
    float4 sh = *(const float4*)(shift + c);
    v.x = fmaxf(fmaf(v.x, sc.x, sh.x), 0.f);
    v.y = fmaxf(fmaf(v.y, sc.y, sh.y), 0.f);
    v.z = fmaxf(fmaf(v.z, sc.z, sh.z), 0.f);
    v.w = fmaxf(fmaf(v.w, sc.w, sh.w), 0.f);
    ((float4*)y)[idx] = v;
}

// ------------------------- SGEMM: C[M,Nc] = A[M,K] @ B[K,Nc] (+bias) --------
#define GBM 128
#define GBN 64
#define GBK 16
__global__ void __launch_bounds__(256) k_gemm(const float* __restrict__ A,
                                              const float* __restrict__ B,
                                              const float* __restrict__ bias,
                                              float* __restrict__ C,
                                              int M, int K, int Nc) {
    __shared__ __align__(16) float As[GBK][GBM + 4];
    __shared__ __align__(16) float Bs[GBK][GBN];
    int tid = threadIdx.x;
    int bm = blockIdx.y * GBM;
    int bn = blockIdx.x * GBN;
    int tx = tid & 15;   // 0..15 -> 4 cols each
    int ty = tid >> 4;   // 0..15 -> 8 rows (stride 16)

    float acc[8][4];
#pragma unroll
    for (int i = 0; i < 8; ++i)
#pragma unroll
        for (int j = 0; j < 4; ++j) acc[i][j] = 0.f;

    int arow0 = tid >> 2;        // 0..63
    int akc = (tid & 3) * 4;     // 0,4,8,12
    int brow = tid >> 4;         // 0..15
    int bcol = (tid & 15) * 4;   // 0..60

    for (int k0 = 0; k0 < K; k0 += GBK) {
#pragma unroll
        for (int h = 0; h < 2; ++h) {
            int r = arow0 + h * 64;
            int gr = bm + r;
            float4 v = make_float4(0.f, 0.f, 0.f, 0.f);
            if (gr < M) v = *(const float4*)(A + (size_t)gr * K + k0 + akc);
            As[akc + 0][r] = v.x;
            As[akc + 1][r] = v.y;
            As[akc + 2][r] = v.z;
            As[akc + 3][r] = v.w;
        }
        float4 bv = *(const float4*)(B + (size_t)(k0 + brow) * Nc + bn + bcol);
        *(float4*)&Bs[brow][bcol] = bv;
        __syncthreads();

#pragma unroll
        for (int k = 0; k < GBK; ++k) {
            float a[8];
#pragma unroll
            for (int i = 0; i < 8; ++i) a[i] = As[k][ty + i * 16];
            float4 bb = *(float4*)&Bs[k][tx * 4];
            float b0 = bb.x, b1 = bb.y, b2 = bb.z, b3 = bb.w;
#pragma unroll
            for (int i = 0; i < 8; ++i) {
                acc[i][0] = fmaf(a[i], b0, acc[i][0]);
                acc[i][1] = fmaf(a[i], b1, acc[i][1]);
                acc[i][2] = fmaf(a[i], b2, acc[i][2]);
                acc[i][3] = fmaf(a[i], b3, acc[i][3]);
            }
        }
        __syncthreads();
    }

    float4 bias4 = make_float4(0.f, 0.f, 0.f, 0.f);
    if (bias) bias4 = *(const float4*)(bias + bn + tx * 4);
#pragma unroll
    for (int i = 0; i < 8; ++i) {
        int gr = bm + ty + i * 16;
        if (gr < M) {
            float4 o;
            o.x = acc[i][0] + bias4.x;
            o.y = acc[i][1] + bias4.y;
            o.z = acc[i][2] + bias4.z;
            o.w = acc[i][3] + bias4.w;
            *(float4*)(C + (size_t)gr * Nc + bn + tx * 4) = o;
        }
    }
}

// ------------------------- host orchestration -------------------------------
static void launch_gemm(const float* A, const float* B, const float* bias,
                        float* C, int M, int K, int Nc) {
    dim3 grid(Nc / GBN, (M + GBM - 1) / GBM);
    k_gemm<<<grid, 256>>>(A, B, bias, C, M, K, Nc);
}

static void launch_bn(const float* x, const float* gamma, const float* beta,
                      float* y, float* sum, float* sumsq, float* scale, float* shift) {
    k_bn_zero<<<1, HC>>>(sum, sumsq);
    k_bn_stats<<<(Nn + 255) / 256, 256>>>(x, sum, sumsq);
    k_bn_finalize<<<1, HC>>>(sum, sumsq, gamma, beta, scale, shift);
    size_t n4 = (size_t)Nn * HC / 4;
    k_bn_apply<<<(unsigned)((n4 + 255) / 256), 256>>>(x, scale, shift, y);
}

extern "C" void kernel_launch(void* const* d_in, const int* in_sizes, int n_in,
                              void* d_out, int out_size) {
    const float* x  = (const float*)d_in[0];
    const void*  ei = d_in[1];
    const float* W1 = (const float*)d_in[2];
    const float* g1 = (const float*)d_in[4];
    const float* be1 = (const float*)d_in[5];
    const float* W2 = (const float*)d_in[6];
    const float* g2 = (const float*)d_in[8];
    const float* be2 = (const float*)d_in[9];
    const float* W3 = (const float*)d_in[10];
    const float* b3 = (const float*)d_in[11];
    const float* dW1 = (const float*)d_in[12];
    const float* dg1 = (const float*)d_in[14];
    const float* dbe1 = (const float*)d_in[15];
    const float* dW2 = (const float*)d_in[16];
    const float* dg2 = (const float*)d_in[18];
    const float* dbe2 = (const float*)d_in[19];
    const float* dW3 = (const float*)d_in[20];
    const float* db3 = (const float*)d_in[21];

    float* out  = (float*)d_out;
    float* xhat = out;                                  // [Nn, INC]
    float* zout = out + (size_t)Nn * INC;               // [Nn, LC]

    float *bufA, *bufB, *bufC, *zbuf, *dinv, *fsum, *fsumsq, *fscale, *fshift;
    int *cnt, *rowstart, *wr, *colarr;
    cudaGetSymbolAddress((void**)&bufA, g_bufA);
    cudaGetSymbolAddress((void**)&bufB, g_bufB);
    cudaGetSymbolAddress((void**)&bufC, g_bufC);
    cudaGetSymbolAddress((void**)&zbuf, g_zbuf);
    cudaGetSymbolAddress((void**)&dinv, g_dinv);
    cudaGetSymbolAddress((void**)&cnt, g_cnt);
    cudaGetSymbolAddress((void**)&rowstart, g_rowstart);
    cudaGetSymbolAddress((void**)&wr, g_wr);
    cudaGetSymbolAddress((void**)&colarr, g_col);
    cudaGetSymbolAddress((void**)&fsum, g_sum);
    cudaGetSymbolAddress((void**)&fsumsq, g_sumsq);
    cudaGetSymbolAddress((void**)&fscale, g_scale);
    cudaGetSymbolAddress((void**)&fshift, g_shift);

    // ---- edge dtype detection + degree + CSR build ----
    k_detect<<<1, 256>>>((const long long*)ei);
    k_zero_int<<<(Nn + 255) / 256, 256>>>(cnt, Nn);
    k_hist<<<(Ed + 255) / 256, 256>>>(ei, cnt);
    k_dinv<<<(Nn + 255) / 256, 256>>>(cnt, dinv);
    k_scan<<<1, 1024>>>(cnt, rowstart, wr, Nn);
    k_scatter<<<(Ed + 255) / 256, 256>>>(ei, wr, colarr);

    const int aggBlocks256 = (Nn * 32 + 255) / 256;

    // ---- encoder layer 1: h = BNrelu(agg(x@W1)) ----  (bias before BN cancels)
    launch_gemm(x, W1, nullptr, bufA, Nn, INC, HC);
    k_agg<256><<<aggBlocks256, 256>>>(bufA, rowstart, colarr, dinv, nullptr, bufB);
    launch_bn(bufB, g1, be1, bufC, fsum, fsumsq, fscale, fshift);

    // ---- encoder layer 2 ----
    launch_gemm(bufC, W2, nullptr, bufA, Nn, HC, HC);
    k_agg<256><<<aggBlocks256, 256>>>(bufA, rowstart, colarr, dinv, nullptr, bufB);
    launch_bn(bufB, g2, be2, bufC, fsum, fsumsq, fscale, fshift);

    // ---- encoder layer 3: z = agg(h@W3) + b3 ----
    launch_gemm(bufC, W3, nullptr, zbuf, Nn, HC, LC);
    k_agg<64><<<aggBlocks256, 256>>>(zbuf, rowstart, colarr, dinv, b3, zout);

    // ---- decoder ----
    launch_gemm(zout, dW1, nullptr, bufA, Nn, LC, HC);
    launch_bn(bufA, dg1, dbe1, bufB, fsum, fsumsq, fscale, fshift);

    launch_gemm(bufB, dW2, nullptr, bufC, Nn, HC, HC);
    launch_bn(bufC, dg2, dbe2, bufA, fsum, fsumsq, fscale, fshift);

    launch_gemm(bufA, dW3, db3, xhat, Nn, HC, INC);
}

// round 6
// speedup vs baseline: 1.3797x; 1.3797x over previous
#include <cuda_runtime.h>
#include <cuda_bf16.h>
#include <cstdint>
#include <cstddef>

#define Nn   100000
#define Ed   1600000
#define INC  128
#define HC   256
#define LC   64
#define EPSB 1e-5f

// ===================== pack / unpack (bf16 hi/lo split) ======================
__device__ __forceinline__ uint32_t pack2(float v) {
    __nv_bfloat16 h = __float2bfloat16(v);
    float hf = __bfloat162float(h);
    __nv_bfloat16 l = __float2bfloat16(v - hf);
    return (uint32_t)__bfloat16_as_ushort(h) | ((uint32_t)__bfloat16_as_ushort(l) << 16);
}
__device__ __forceinline__ float unpack2(uint32_t p) {
    return __bfloat162float(__ushort_as_bfloat16((unsigned short)(p & 0xFFFFu))) +
           __bfloat162float(__ushort_as_bfloat16((unsigned short)(p >> 16)));
}

// ===================== scratch (device globals) ==============================
__device__ float    g_bufA[(size_t)Nn * HC];     // fp32 GEMM output
__device__ uint32_t g_packP1[(size_t)Nn * HC];   // packed bf16-split
__device__ uint32_t g_packP2[(size_t)Nn * HC];
__device__ float    g_zbuf[(size_t)Nn * LC];
__device__ uint32_t g_zsp[(size_t)Nn * LC];
__device__ uint32_t g_wsplit[229376];            // all 6 weights, transposed+split
__device__ float    g_dinv[Nn];
__device__ int      g_cnt[Nn];
__device__ int      g_rowstart[Nn + 1];
__device__ int      g_wr[Nn];
__device__ int      g_col[Ed];
__device__ float    g_sum[HC];
__device__ float    g_sumsq[HC];
__device__ float    g_scale[HC];
__device__ float    g_shift[HC];
__device__ int      g_is32;

// weight-split offsets within g_wsplit (u32 elems, layout [N][K])
#define WOFF_1 0        /* 256x128 */
#define WOFF_2 32768    /* 256x256 */
#define WOFF_3 98304    /* 64x256  */
#define WOFF_4 114688   /* 256x64  */
#define WOFF_5 131072   /* 256x256 */
#define WOFF_6 196608   /* 128x256 */

// ===================== edge dtype detection / CSR build ======================
__global__ void k_detect(const long long* __restrict__ ei64) {
    __shared__ int s_bad;
    if (threadIdx.x == 0) s_bad = 0;
    __syncthreads();
    long long v0 = ei64[threadIdx.x];
    long long v1 = ei64[(size_t)Ed + threadIdx.x];
    if (v0 < 0 || v0 >= (long long)Nn || v1 < 0 || v1 >= (long long)Nn) atomicOr(&s_bad, 1);
    __syncthreads();
    if (threadIdx.x == 0) g_is32 = s_bad ? 1 : 0;
}

__device__ __forceinline__ int edge_at(const void* ei, int is32, size_t pos) {
    if (is32) return ((const int*)ei)[pos];
    return (int)((const long long*)ei)[pos];
}

__global__ void k_zero_int(int* p, int n) {
    int i = blockIdx.x * blockDim.x + threadIdx.x;
    if (i < n) p[i] = 0;
}

__global__ void k_hist(const void* __restrict__ ei, int* __restrict__ cnt) {
    int e = blockIdx.x * blockDim.x + threadIdx.x;
    if (e >= Ed) return;
    int dst = edge_at(ei, g_is32, (size_t)Ed + e);
    if ((unsigned)dst < (unsigned)Nn) atomicAdd(&cnt[dst], 1);
}

__global__ void k_dinv(const int* __restrict__ cnt, float* __restrict__ dinv) {
    int i = blockIdx.x * blockDim.x + threadIdx.x;
    if (i < Nn) dinv[i] = rsqrtf((float)(cnt[i] + 1));
}

__global__ void __launch_bounds__(1024) k_scan(const int* __restrict__ cnt,
                                               int* __restrict__ rowstart,
                                               int* __restrict__ wr, int n) {
    __shared__ int sh[1024];
    __shared__ int s_carry;
    int tid = threadIdx.x;
    if (tid == 0) s_carry = 0;
    __syncthreads();
    for (int base = 0; base < n; base += 1024) {
        int i = base + tid;
        int v = (i < n) ? cnt[i] : 0;
        sh[tid] = v;
        __syncthreads();
        for (int off = 1; off < 1024; off <<= 1) {
            int t = (tid >= off) ? sh[tid - off] : 0;
            __syncthreads();
            sh[tid] += t;
            __syncthreads();
        }
        int incl = sh[tid];
        int excl = incl - v;
        int carry = s_carry;
        if (i < n) { rowstart[i] = carry + excl; wr[i] = carry + excl; }
        __syncthreads();
        if (tid == 1023) s_carry = carry + incl;
        __syncthreads();
    }
    if (tid == 0) rowstart[n] = (s_carry <= Ed) ? s_carry : Ed;
}

__global__ void k_scatter(const void* __restrict__ ei,
                          int* __restrict__ wr, int* __restrict__ col) {
    int e = blockIdx.x * blockDim.x + threadIdx.x;
    if (e >= Ed) return;
    int is32 = g_is32;
    int src = edge_at(ei, is32, (size_t)e);
    int dst = edge_at(ei, is32, (size_t)Ed + e);
    if ((unsigned)dst >= (unsigned)Nn || (unsigned)src >= (unsigned)Nn) return;
    int pos = atomicAdd(&wr[dst], 1);
    if ((unsigned)pos < (unsigned)Ed) col[pos] = src;
}

// ===================== weight transpose + split ==============================
// W [K,N] fp32 row-major -> out [N][K] packed u32
__global__ void k_wsplit(const float* __restrict__ W, uint32_t* __restrict__ out, int K, int N) {
    int idx = blockIdx.x * blockDim.x + threadIdx.x;
    if (idx >= K * N) return;
    int k = idx / N, n = idx % N;
    out[(size_t)n * K + k] = pack2(W[idx]);
}

// ===================== aggregations (one warp per node) ======================
__global__ void __launch_bounds__(256) k_agg_f2p128(const float* __restrict__ h,
                                                    const int* __restrict__ rowstart,
                                                    const int* __restrict__ col,
                                                    const float* __restrict__ dinv,
                                                    uint32_t* __restrict__ outp) {
    int warp = (blockIdx.x * blockDim.x + threadIdx.x) >> 5;
    int lane = threadIdx.x & 31;
    if (warp >= Nn) return;
    float di = dinv[warp];
    int jb = rowstart[warp], je = rowstart[warp + 1];
    const float4* h4 = (const float4*)h;  // 32 float4 per row
    float cs = di * di;
    float4 x = h4[(size_t)warp * 32 + lane];
    float4 a = make_float4(cs * x.x, cs * x.y, cs * x.z, cs * x.w);
    for (int j = jb; j < je; ++j) {
        int s = col[j];
        float c = di * dinv[s];
        float4 y = h4[(size_t)s * 32 + lane];
        a.x += c * y.x; a.y += c * y.y; a.z += c * y.z; a.w += c * y.w;
    }
    uint4 o = make_uint4(pack2(a.x), pack2(a.y), pack2(a.z), pack2(a.w));
    ((uint4*)outp)[(size_t)warp * 32 + lane] = o;
}

__global__ void __launch_bounds__(256) k_agg_p2p256(const uint32_t* __restrict__ hp,
                                                    const int* __restrict__ rowstart,
                                                    const int* __restrict__ col,
                                                    const float* __restrict__ dinv,
                                                    uint32_t* __restrict__ outp) {
    int warp = (blockIdx.x * blockDim.x + threadIdx.x) >> 5;
    int lane = threadIdx.x & 31;
    if (warp >= Nn) return;
    float di = dinv[warp];
    int jb = rowstart[warp], je = rowstart[warp + 1];
    const uint4* h4 = (const uint4*)hp;  // 64 uint4 per row
    float cs = di * di;
    float a[8];
    {
        uint4 q0 = h4[(size_t)warp * 64 + lane];
        uint4 q1 = h4[(size_t)warp * 64 + lane + 32];
        a[0] = cs * unpack2(q0.x); a[1] = cs * unpack2(q0.y);
        a[2] = cs * unpack2(q0.z); a[3] = cs * unpack2(q0.w);
        a[4] = cs * unpack2(q1.x); a[5] = cs * unpack2(q1.y);
        a[6] = cs * unpack2(q1.z); a[7] = cs * unpack2(q1.w);
    }
    for (int j = jb; j < je; ++j) {
        int s = col[j];
        float c = di * dinv[s];
        uint4 y0 = h4[(size_t)s * 64 + lane];
        uint4 y1 = h4[(size_t)s * 64 + lane + 32];
        a[0] += c * unpack2(y0.x); a[1] += c * unpack2(y0.y);
        a[2] += c * unpack2(y0.z); a[3] += c * unpack2(y0.w);
        a[4] += c * unpack2(y1.x); a[5] += c * unpack2(y1.y);
        a[6] += c * unpack2(y1.z); a[7] += c * unpack2(y1.w);
    }
    uint4 o0 = make_uint4(pack2(a[0]), pack2(a[1]), pack2(a[2]), pack2(a[3]));
    uint4 o1 = make_uint4(pack2(a[4]), pack2(a[5]), pack2(a[6]), pack2(a[7]));
    ((uint4*)outp)[(size_t)warp * 64 + lane] = o0;
    ((uint4*)outp)[(size_t)warp * 64 + lane + 32] = o1;
}

__global__ void __launch_bounds__(256) k_agg_z64(const float* __restrict__ h,
                                                 const int* __restrict__ rowstart,
                                                 const int* __restrict__ col,
                                                 const float* __restrict__ dinv,
                                                 const float* __restrict__ bias,
                                                 float* __restrict__ zout,
                                                 uint32_t* __restrict__ zsp) {
    int warp = (blockIdx.x * blockDim.x + threadIdx.x) >> 5;
    int lane = threadIdx.x & 31;
    if (warp >= Nn) return;
    float di = dinv[warp];
    int jb = rowstart[warp], je = rowstart[warp + 1];
    const float2* h2 = (const float2*)h;  // 32 float2 per row
    float cs = di * di;
    float2 x = h2[(size_t)warp * 32 + lane];
    float2 a = make_float2(cs * x.x, cs * x.y);
    for (int j = jb; j < je; ++j) {
        int s = col[j];
        float c = di * dinv[s];
        float2 y = h2[(size_t)s * 32 + lane];
        a.x += c * y.x; a.y += c * y.y;
    }
    float2 b = *(const float2*)(bias + lane * 2);
    a.x += b.x; a.y += b.y;
    ((float2*)zout)[(size_t)warp * 32 + lane] = a;
    ((uint2*)zsp)[(size_t)warp * 32 + lane] = make_uint2(pack2(a.x), pack2(a.y));
}

// ===================== BatchNorm =============================================
__global__ void k_bn_zero(float* sum, float* sumsq) {
    int c = threadIdx.x;
    sum[c] = 0.f; sumsq[c] = 0.f;
}

__global__ void __launch_bounds__(256) k_bn_stats(const float* __restrict__ x,
                                                  float* __restrict__ sum,
                                                  float* __restrict__ sumsq) {
    int colc = threadIdx.x;
    int r0 = blockIdx.x * 256;
    int rend = min(r0 + 256, Nn);
    float s = 0.f, ss = 0.f;
    for (int r = r0; r < rend; ++r) {
        float v = x[(size_t)r * HC + colc];
        s += v; ss += v * v;
    }
    atomicAdd(&sum[colc], s);
    atomicAdd(&sumsq[colc], ss);
}

__global__ void k_bn_finalize(const float* __restrict__ sum, const float* __restrict__ sumsq,
                              const float* __restrict__ gamma, const float* __restrict__ beta,
                              float* __restrict__ scale, float* __restrict__ shift) {
    int c = threadIdx.x;
    float invM = 1.f / (float)Nn;
    float m = sum[c] * invM;
    float v = fmaxf(sumsq[c] * invM - m * m, 0.f);
    float sc = gamma[c] * rsqrtf(v + EPSB);
    scale[c] = sc;
    shift[c] = beta[c] - m * sc;
}

// y = pack(relu(x*scale + shift))
__global__ void __launch_bounds__(256) k_bn_apply_pack(const float* __restrict__ x,
                                                       const float* __restrict__ scale,
                                                       const float* __restrict__ shift,
                                                       uint32_t* __restrict__ yp) {
    size_t idx = (size_t)blockIdx.x * blockDim.x + threadIdx.x;
    size_t n4 = (size_t)Nn * HC / 4;
    if (idx >= n4) return;
    int c = ((int)(idx & 63)) * 4;
    float4 v = ((const float4*)x)[idx];
    float4 sc = *(const float4*)(scale + c);
    float4 sh = *(const float4*)(shift + c);
    float t0 = fmaxf(fmaf(v.x, sc.x, sh.x), 0.f);
    float t1 = fmaxf(fmaf(v.y, sc.y, sh.y), 0.f);
    float t2 = fmaxf(fmaf(v.z, sc.z, sh.z), 0.f);
    float t3 = fmaxf(fmaf(v.w, sc.w, sh.w), 0.f);
    ((uint4*)yp)[idx] = make_uint4(pack2(t0), pack2(t1), pack2(t2), pack2(t3));
}

// ===================== mma.sync bf16 GEMM ====================================
// C[M,NT] = unpack(Ap)[M,KT] @ unpack(Bp)[NT,KT]^T (+bias)
// Compensated: Ahi*Bhi + Ahi*Blo + Alo*Bhi (fp32 accumulate).
__device__ __forceinline__ void mma16816(float* acc, const uint32_t* a, const uint32_t* b) {
    asm volatile(
        "mma.sync.aligned.m16n8k16.row.col.f32.bf16.bf16.f32 "
        "{%0,%1,%2,%3}, {%4,%5,%6,%7}, {%8,%9}, {%0,%1,%2,%3};"
        : "+f"(acc[0]), "+f"(acc[1]), "+f"(acc[2]), "+f"(acc[3])
        : "r"(a[0]), "r"(a[1]), "r"(a[2]), "r"(a[3]), "r"(b[0]), "r"(b[1]));
}

template <int KT, int NT, bool HAS_BIAS>
__global__ void __launch_bounds__(256) k_mma(const uint32_t* __restrict__ Ap,
                                             const uint32_t* __restrict__ Bp,
                                             const float* __restrict__ bias,
                                             float* __restrict__ C) {
    constexpr int M = Nn;
    __shared__ __nv_bfloat16 Ahi[128][40];
    __shared__ __nv_bfloat16 Alo[128][40];
    __shared__ __nv_bfloat16 Bhi[64][40];
    __shared__ __nv_bfloat16 Blo[64][40];

    int tid = threadIdx.x;
    int wid = tid >> 5, lane = tid & 31;
    int g = lane >> 2, tig = lane & 3;
    int warp_m = wid & 3, warp_n = wid >> 2;
    int bm = blockIdx.y * 128, bn = blockIdx.x * 64;

    float acc[2][4][4];
#pragma unroll
    for (int mt = 0; mt < 2; ++mt)
#pragma unroll
        for (int nt = 0; nt < 4; ++nt)
#pragma unroll
            for (int i = 0; i < 4; ++i) acc[mt][nt][i] = 0.f;

    for (int ch = 0; ch < KT / 32; ++ch) {
        const int k0 = ch * 32;
        // ---- stage A: 128 rows x 32 packed u32 -> Ahi/Alo
        {
            int r = tid >> 1;
            int koff = (tid & 1) * 16;
            bool valid = (bm + r) < M;
            uint4 v[4];
            if (valid) {
                const uint4* src = (const uint4*)(Ap + (size_t)(bm + r) * KT + k0 + koff);
#pragma unroll
                for (int q = 0; q < 4; ++q) v[q] = src[q];
            } else {
#pragma unroll
                for (int q = 0; q < 4; ++q) v[q] = make_uint4(0u, 0u, 0u, 0u);
            }
            const uint32_t* p = (const uint32_t*)v;
#pragma unroll
            for (int i = 0; i < 16; i += 2) {
                uint32_t p0 = p[i], p1 = p[i + 1];
                *(uint32_t*)&Ahi[r][koff + i] = (p0 & 0xFFFFu) | (p1 << 16);
                *(uint32_t*)&Alo[r][koff + i] = (p0 >> 16) | (p1 & 0xFFFF0000u);
            }
        }
        // ---- stage B: 64 rows x 32 packed u32 -> Bhi/Blo
        {
            int n = tid >> 2;
            int koff = (tid & 3) * 8;
            const uint4* src = (const uint4*)(Bp + (size_t)(bn + n) * KT + k0 + koff);
            uint4 v0 = src[0], v1 = src[1];
            uint32_t p[8] = {v0.x, v0.y, v0.z, v0.w, v1.x, v1.y, v1.z, v1.w};
#pragma unroll
            for (int i = 0; i < 8; i += 2) {
                uint32_t p0 = p[i], p1 = p[i + 1];
                *(uint32_t*)&Bhi[n][koff + i] = (p0 & 0xFFFFu) | (p1 << 16);
                *(uint32_t*)&Blo[n][koff + i] = (p0 >> 16) | (p1 & 0xFFFF0000u);
            }
        }
        __syncthreads();

#pragma unroll
        for (int kk = 0; kk < 32; kk += 16) {
            uint32_t ah[2][4], al[2][4], bh[4][2], bl[4][2];
            int cA = kk + tig * 2;
#pragma unroll
            for (int mt = 0; mt < 2; ++mt) {
                int r0 = warp_m * 32 + mt * 16 + g;
                ah[mt][0] = *(const uint32_t*)&Ahi[r0][cA];
                ah[mt][1] = *(const uint32_t*)&Ahi[r0 + 8][cA];
                ah[mt][2] = *(const uint32_t*)&Ahi[r0][cA + 8];
                ah[mt][3] = *(const uint32_t*)&Ahi[r0 + 8][cA + 8];
                al[mt][0] = *(const uint32_t*)&Alo[r0][cA];
                al[mt][1] = *(const uint32_t*)&Alo[r0 + 8][cA];
                al[mt][2] = *(const uint32_t*)&Alo[r0][cA + 8];
                al[mt][3] = *(const uint32_t*)&Alo[r0 + 8][cA + 8];
            }
#pragma unroll
            for (int nt = 0; nt < 4; ++nt) {
                int n0 = warp_n * 32 + nt * 8 + g;
                bh[nt][0] = *(const uint32_t*)&Bhi[n0][cA];
                bh[nt][1] = *(const uint32_t*)&Bhi[n0][cA + 8];
                bl[nt][0] = *(const uint32_t*)&Blo[n0][cA];
                bl[nt][1] = *(const uint32_t*)&Blo[n0][cA + 8];
            }
#pragma unroll
            for (int mt = 0; mt < 2; ++mt)
#pragma unroll
                for (int nt = 0; nt < 4; ++nt) {
                    mma16816(acc[mt][nt], ah[mt], bh[nt]);
                    mma16816(acc[mt][nt], ah[mt], bl[nt]);
                    mma16816(acc[mt][nt], al[mt], bh[nt]);
                }
        }
        __syncthreads();
    }

    // ---- epilogue
#pragma unroll
    for (int mt = 0; mt < 2; ++mt) {
        int r0 = bm + warp_m * 32 + mt * 16 + g;
#pragma unroll
        for (int nt = 0; nt < 4; ++nt) {
            int cc = bn + warp_n * 32 + nt * 8 + tig * 2;
            float b0 = 0.f, b1 = 0.f;
            if (HAS_BIAS) { b0 = bias[cc]; b1 = bias[cc + 1]; }
            if (r0 < M) {
                float2 v = make_float2(acc[mt][nt][0] + b0, acc[mt][nt][1] + b1);
                *(float2*)(C + (size_t)r0 * NT + cc) = v;
            }
            if (r0 + 8 < M) {
                float2 v = make_float2(acc[mt][nt][2] + b0, acc[mt][nt][3] + b1);
                *(float2*)(C + (size_t)(r0 + 8) * NT + cc) = v;
            }
        }
    }
}

// ===================== host orchestration ====================================
template <int KT, int NT, bool HAS_BIAS>
static void launch_mma(const uint32_t* Ap, const uint32_t* Bp, const float* bias, float* C) {
    dim3 grid(NT / 64, (Nn + 127) / 128);
    k_mma<KT, NT, HAS_BIAS><<<grid, 256>>>(Ap, Bp, bias, C);
}

static void launch_bn_pack(const float* x, const float* gamma, const float* beta,
                           uint32_t* yp, float* sum, float* sumsq, float* scale, float* shift) {
    k_bn_zero<<<1, HC>>>(sum, sumsq);
    k_bn_stats<<<(Nn + 255) / 256, 256>>>(x, sum, sumsq);
    k_bn_finalize<<<1, HC>>>(sum, sumsq, gamma, beta, scale, shift);
    size_t n4 = (size_t)Nn * HC / 4;
    k_bn_apply_pack<<<(unsigned)((n4 + 255) / 256), 256>>>(x, scale, shift, yp);
}

extern "C" void kernel_launch(void* const* d_in, const int* in_sizes, int n_in,
                              void* d_out, int out_size) {
    const float* x  = (const float*)d_in[0];
    const void*  ei = d_in[1];
    const float* W1 = (const float*)d_in[2];
    const float* g1 = (const float*)d_in[4];
    const float* be1 = (const float*)d_in[5];
    const float* W2 = (const float*)d_in[6];
    const float* g2 = (const float*)d_in[8];
    const float* be2 = (const float*)d_in[9];
    const float* W3 = (const float*)d_in[10];
    const float* b3 = (const float*)d_in[11];
    const float* dW1 = (const float*)d_in[12];
    const float* dg1 = (const float*)d_in[14];
    const float* dbe1 = (const float*)d_in[15];
    const float* dW2 = (const float*)d_in[16];
    const float* dg2 = (const float*)d_in[18];
    const float* dbe2 = (const float*)d_in[19];
    const float* dW3 = (const float*)d_in[20];
    const float* db3 = (const float*)d_in[21];

    float* out  = (float*)d_out;
    float* xhat = out;                           // [Nn, INC]
    float* zout = out + (size_t)Nn * INC;        // [Nn, LC]

    float *bufA, *zbuf, *dinv, *fsum, *fsumsq, *fscale, *fshift;
    uint32_t *P1, *P2, *zsp, *wsp;
    int *cnt, *rowstart, *wr, *colarr;
    cudaGetSymbolAddress((void**)&bufA, g_bufA);
    cudaGetSymbolAddress((void**)&P1, g_packP1);
    cudaGetSymbolAddress((void**)&P2, g_packP2);
    cudaGetSymbolAddress((void**)&zbuf, g_zbuf);
    cudaGetSymbolAddress((void**)&zsp, g_zsp);
    cudaGetSymbolAddress((void**)&wsp, g_wsplit);
    cudaGetSymbolAddress((void**)&dinv, g_dinv);
    cudaGetSymbolAddress((void**)&cnt, g_cnt);
    cudaGetSymbolAddress((void**)&rowstart, g_rowstart);
    cudaGetSymbolAddress((void**)&wr, g_wr);
    cudaGetSymbolAddress((void**)&colarr, g_col);
    cudaGetSymbolAddress((void**)&fsum, g_sum);
    cudaGetSymbolAddress((void**)&fsumsq, g_sumsq);
    cudaGetSymbolAddress((void**)&fscale, g_scale);
    cudaGetSymbolAddress((void**)&fshift, g_shift);

    // ---- edge dtype detection + CSR build ----
    k_detect<<<1, 256>>>((const long long*)ei);
    k_zero_int<<<(Nn + 255) / 256, 256>>>(cnt, Nn);
    k_hist<<<(Ed + 255) / 256, 256>>>(ei, cnt);
    k_dinv<<<(Nn + 255) / 256, 256>>>(cnt, dinv);
    k_scan<<<1, 1024>>>(cnt, rowstart, wr, Nn);
    k_scatter<<<(Ed + 255) / 256, 256>>>(ei, wr, colarr);

    // ---- weight transpose + split (tiny) ----
    k_wsplit<<<(INC * HC + 255) / 256, 256>>>(W1,  wsp + WOFF_1, INC, HC);
    k_wsplit<<<(HC * HC + 255) / 256, 256>>>(W2,  wsp + WOFF_2, HC, HC);
    k_wsplit<<<(HC * LC + 255) / 256, 256>>>(W3,  wsp + WOFF_3, HC, LC);
    k_wsplit<<<(LC * HC + 255) / 256, 256>>>(dW1, wsp + WOFF_4, LC, HC);
    k_wsplit<<<(HC * HC + 255) / 256, 256>>>(dW2, wsp + WOFF_5, HC, HC);
    k_wsplit<<<(HC * INC + 255) / 256, 256>>>(dW3, wsp + WOFF_6, HC, INC);

    const int aggBlocks = (Nn * 32 + 255) / 256;

    // ---- encoder layer 1:  h1 = BNrelu( agg(x) @ W1 )   (agg/GEMM swapped) ----
    k_agg_f2p128<<<aggBlocks, 256>>>(x, rowstart, colarr, dinv, P2);
    launch_mma<INC, HC, false>(P2, wsp + WOFF_1, nullptr, bufA);
    launch_bn_pack(bufA, g1, be1, P1, fsum, fsumsq, fscale, fshift);

    // ---- encoder layer 2:  h2 = BNrelu( agg(h1) @ W2 ) ----
    k_agg_p2p256<<<aggBlocks, 256>>>(P1, rowstart, colarr, dinv, P2);
    launch_mma<HC, HC, false>(P2, wsp + WOFF_2, nullptr, bufA);
    launch_bn_pack(bufA, g2, be2, P1, fsum, fsumsq, fscale, fshift);

    // ---- encoder layer 3:  z = agg(h2 @ W3) + b3 ----
    launch_mma<HC, LC, false>(P1, wsp + WOFF_3, nullptr, zbuf);
    k_agg_z64<<<aggBlocks, 256>>>(zbuf, rowstart, colarr, dinv, b3, zout, zsp);

    // ---- decoder ----
    launch_mma<LC, HC, false>(zsp, wsp + WOFF_4, nullptr, bufA);
    launch_bn_pack(bufA, dg1, dbe1, P1, fsum, fsumsq, fscale, fshift);

    launch_mma<HC, HC, false>(P1, wsp + WOFF_5, nullptr, bufA);
    launch_bn_pack(bufA, dg2, dbe2, P2, fsum, fsumsq, fscale, fshift);

    launch_mma<HC, INC, true>(P2, wsp + WOFF_6, db3, xhat);
}

// round 7
// speedup vs baseline: 1.5551x; 1.1271x over previous
#include <cuda_runtime.h>
#include <cuda_bf16.h>
#include <cstdint>
#include <cstddef>

#define Nn   100000
#define Ed   1600000
#define INC  128
#define HC   256
#define LC   64
#define EPSB 1e-5f
#define SCAN_NB ((Nn + 1023) / 1024)   /* 98 */

// ===================== pack / unpack (bf16 hi/lo split) ======================
__device__ __forceinline__ uint32_t pack2(float v) {
    __nv_bfloat16 h = __float2bfloat16(v);
    float hf = __bfloat162float(h);
    __nv_bfloat16 l = __float2bfloat16(v - hf);
    return (uint32_t)__bfloat16_as_ushort(h) | ((uint32_t)__bfloat16_as_ushort(l) << 16);
}
__device__ __forceinline__ float unpack2(uint32_t p) {
    return __bfloat162float(__ushort_as_bfloat16((unsigned short)(p & 0xFFFFu))) +
           __bfloat162float(__ushort_as_bfloat16((unsigned short)(p >> 16)));
}

// ===================== scratch (device globals) ==============================
__device__ float    g_bufA[(size_t)Nn * HC];     // fp32 GEMM output
__device__ uint32_t g_packP1[(size_t)Nn * HC];   // packed bf16-split
__device__ uint32_t g_packP2[(size_t)Nn * HC];
__device__ float    g_zbuf[(size_t)Nn * LC];
__device__ uint32_t g_zsp[(size_t)Nn * LC];
__device__ uint32_t g_wsplit[229376];            // all 6 weights, transposed+split
__device__ float    g_dinv[Nn];
__device__ int      g_cnt[Nn];
__device__ int      g_rowstart[Nn + 1];
__device__ int      g_wr[Nn];
__device__ int      g_col[Ed];
__device__ int      g_partial[SCAN_NB];
__device__ float    g_bnsum[4 * HC];             // 4 BN stat sets
__device__ float    g_bnsumsq[4 * HC];
__device__ float    g_scale[HC];
__device__ float    g_shift[HC];
__device__ int      g_is32;

// weight-split offsets within g_wsplit (u32 elems, layout [N][K])
#define WOFF_1 0        /* 256x128 */
#define WOFF_2 32768    /* 256x256 */
#define WOFF_3 98304    /* 64x256  */
#define WOFF_4 114688   /* 256x64  */
#define WOFF_5 131072   /* 256x256 */
#define WOFF_6 196608   /* 128x256 */

// ===================== edge dtype detection / CSR build ======================
__global__ void k_detect(const long long* __restrict__ ei64) {
    __shared__ int s_bad;
    if (threadIdx.x == 0) s_bad = 0;
    __syncthreads();
    long long v0 = ei64[threadIdx.x];
    long long v1 = ei64[(size_t)Ed + threadIdx.x];
    if (v0 < 0 || v0 >= (long long)Nn || v1 < 0 || v1 >= (long long)Nn) atomicOr(&s_bad, 1);
    __syncthreads();
    if (threadIdx.x == 0) g_is32 = s_bad ? 1 : 0;
}

__device__ __forceinline__ int edge_at(const void* ei, int is32, size_t pos) {
    if (is32) return ((const int*)ei)[pos];
    return (int)((const long long*)ei)[pos];
}

// zero cnt + BN stat buffers in one launch
__global__ void k_zero_all(int* cnt, float* bnsum, float* bnsumsq) {
    int i = blockIdx.x * blockDim.x + threadIdx.x;
    if (i < Nn) cnt[i] = 0;
    if (i < 4 * HC) { bnsum[i] = 0.f; bnsumsq[i] = 0.f; }
}

__global__ void k_hist(const void* __restrict__ ei, int* __restrict__ cnt) {
    int e = blockIdx.x * blockDim.x + threadIdx.x;
    if (e >= Ed) return;
    int dst = edge_at(ei, g_is32, (size_t)Ed + e);
    if ((unsigned)dst < (unsigned)Nn) atomicAdd(&cnt[dst], 1);
}

__global__ void k_dinv(const int* __restrict__ cnt, float* __restrict__ dinv) {
    int i = blockIdx.x * blockDim.x + threadIdx.x;
    if (i < Nn) dinv[i] = rsqrtf((float)(cnt[i] + 1));
}

// ---- parallel 3-phase exclusive scan ----------------------------------------
__global__ void __launch_bounds__(1024) k_blocksum(const int* __restrict__ cnt,
                                                   int* __restrict__ partial) {
    int i = blockIdx.x * 1024 + threadIdx.x;
    int v = (i < Nn) ? cnt[i] : 0;
    for (int o = 16; o; o >>= 1) v += __shfl_down_sync(0xFFFFFFFFu, v, o);
    __shared__ int ws[32];
    if ((threadIdx.x & 31) == 0) ws[threadIdx.x >> 5] = v;
    __syncthreads();
    if (threadIdx.x < 32) {
        int t = ws[threadIdx.x];
        for (int o = 16; o; o >>= 1) t += __shfl_down_sync(0xFFFFFFFFu, t, o);
        if (threadIdx.x == 0) partial[blockIdx.x] = t;
    }
}

__global__ void k_scanpartial(int* __restrict__ partial, int* __restrict__ rowlast) {
    // single block; 98 elements — serial scan by thread 0 is trivial
    if (threadIdx.x == 0) {
        int run = 0;
        for (int b = 0; b < SCAN_NB; ++b) {
            int t = partial[b];
            partial[b] = run;
            run += t;
        }
        rowlast[0] = (run <= Ed) ? run : Ed;
    }
}

__global__ void __launch_bounds__(1024) k_scanlocal(const int* __restrict__ cnt,
                                                    const int* __restrict__ partial,
                                                    int* __restrict__ rowstart,
                                                    int* __restrict__ wr) {
    int i = blockIdx.x * 1024 + threadIdx.x;
    int v = (i < Nn) ? cnt[i] : 0;
    int lane = threadIdx.x & 31, w = threadIdx.x >> 5;
    int incl = v;
    for (int o = 1; o < 32; o <<= 1) {
        int t = __shfl_up_sync(0xFFFFFFFFu, incl, o);
        if (lane >= o) incl += t;
    }
    __shared__ int ws[32];
    if (lane == 31) ws[w] = incl;
    __syncthreads();
    if (threadIdx.x < 32) {
        int t = ws[threadIdx.x];
        int sc = t;
        for (int o = 1; o < 32; o <<= 1) {
            int u = __shfl_up_sync(0xFFFFFFFFu, sc, o);
            if (threadIdx.x >= o) sc += u;
        }
        ws[threadIdx.x] = sc - t;   // exclusive warp offset
    }
    __syncthreads();
    int excl = incl - v + ws[w] + partial[blockIdx.x];
    if (i < Nn) { rowstart[i] = excl; wr[i] = excl; }
}

__global__ void k_scatter(const void* __restrict__ ei,
                          int* __restrict__ wr, int* __restrict__ col) {
    int e = blockIdx.x * blockDim.x + threadIdx.x;
    if (e >= Ed) return;
    int is32 = g_is32;
    int src = edge_at(ei, is32, (size_t)e);
    int dst = edge_at(ei, is32, (size_t)Ed + e);
    if ((unsigned)dst >= (unsigned)Nn || (unsigned)src >= (unsigned)Nn) return;
    int pos = atomicAdd(&wr[dst], 1);
    if ((unsigned)pos < (unsigned)Ed) col[pos] = src;
}

// ===================== weight transpose + split ==============================
__global__ void k_wsplit(const float* __restrict__ W, uint32_t* __restrict__ out, int K, int N) {
    int idx = blockIdx.x * blockDim.x + threadIdx.x;
    if (idx >= K * N) return;
    int k = idx / N, n = idx % N;
    out[(size_t)n * K + k] = pack2(W[idx]);
}

// ===================== aggregations (one warp per node) ======================
__global__ void __launch_bounds__(256) k_agg_f2p128(const float* __restrict__ h,
                                                    const int* __restrict__ rowstart,
                                                    const int* __restrict__ col,
                                                    const float* __restrict__ dinv,
                                                    uint32_t* __restrict__ outp) {
    int warp = (blockIdx.x * blockDim.x + threadIdx.x) >> 5;
    int lane = threadIdx.x & 31;
    if (warp >= Nn) return;
    float di = dinv[warp];
    int jb = rowstart[warp], je = rowstart[warp + 1];
    const float4* h4 = (const float4*)h;  // 32 float4 per row
    float cs = di * di;
    float4 x = h4[(size_t)warp * 32 + lane];
    float4 a = make_float4(cs * x.x, cs * x.y, cs * x.z, cs * x.w);
    for (int j = jb; j < je; ++j) {
        int s = col[j];
        float c = di * dinv[s];
        float4 y = h4[(size_t)s * 32 + lane];
        a.x += c * y.x; a.y += c * y.y; a.z += c * y.z; a.w += c * y.w;
    }
    uint4 o = make_uint4(pack2(a.x), pack2(a.y), pack2(a.z), pack2(a.w));
    ((uint4*)outp)[(size_t)warp * 32 + lane] = o;
}

__global__ void __launch_bounds__(256) k_agg_p2p256(const uint32_t* __restrict__ hp,
                                                    const int* __restrict__ rowstart,
                                                    const int* __restrict__ col,
                                                    const float* __restrict__ dinv,
                                                    uint32_t* __restrict__ outp) {
    int warp = (blockIdx.x * blockDim.x + threadIdx.x) >> 5;
    int lane = threadIdx.x & 31;
    if (warp >= Nn) return;
    float di = dinv[warp];
    int jb = rowstart[warp], je = rowstart[warp + 1];
    const uint4* h4 = (const uint4*)hp;  // 64 uint4 per row
    float cs = di * di;
    float a[8];
    {
        uint4 q0 = h4[(size_t)warp * 64 + lane];
        uint4 q1 = h4[(size_t)warp * 64 + lane + 32];
        a[0] = cs * unpack2(q0.x); a[1] = cs * unpack2(q0.y);
        a[2] = cs * unpack2(q0.z); a[3] = cs * unpack2(q0.w);
        a[4] = cs * unpack2(q1.x); a[5] = cs * unpack2(q1.y);
        a[6] = cs * unpack2(q1.z); a[7] = cs * unpack2(q1.w);
    }
    for (int j = jb; j < je; ++j) {
        int s = col[j];
        float c = di * dinv[s];
        uint4 y0 = h4[(size_t)s * 64 + lane];
        uint4 y1 = h4[(size_t)s * 64 + lane + 32];
        a[0] += c * unpack2(y0.x); a[1] += c * unpack2(y0.y);
        a[2] += c * unpack2(y0.z); a[3] += c * unpack2(y0.w);
        a[4] += c * unpack2(y1.x); a[5] += c * unpack2(y1.y);
        a[6] += c * unpack2(y1.z); a[7] += c * unpack2(y1.w);
    }
    uint4 o0 = make_uint4(pack2(a[0]), pack2(a[1]), pack2(a[2]), pack2(a[3]));
    uint4 o1 = make_uint4(pack2(a[4]), pack2(a[5]), pack2(a[6]), pack2(a[7]));
    ((uint4*)outp)[(size_t)warp * 64 + lane] = o0;
    ((uint4*)outp)[(size_t)warp * 64 + lane + 32] = o1;
}

__global__ void __launch_bounds__(256) k_agg_z64(const float* __restrict__ h,
                                                 const int* __restrict__ rowstart,
                                                 const int* __restrict__ col,
                                                 const float* __restrict__ dinv,
                                                 const float* __restrict__ bias,
                                                 float* __restrict__ zout,
                                                 uint32_t* __restrict__ zsp) {
    int warp = (blockIdx.x * blockDim.x + threadIdx.x) >> 5;
    int lane = threadIdx.x & 31;
    if (warp >= Nn) return;
    float di = dinv[warp];
    int jb = rowstart[warp], je = rowstart[warp + 1];
    const float2* h2 = (const float2*)h;  // 32 float2 per row
    float cs = di * di;
    float2 x = h2[(size_t)warp * 32 + lane];
    float2 a = make_float2(cs * x.x, cs * x.y);
    for (int j = jb; j < je; ++j) {
        int s = col[j];
        float c = di * dinv[s];
        float2 y = h2[(size_t)s * 32 + lane];
        a.x += c * y.x; a.y += c * y.y;
    }
    float2 b = *(const float2*)(bias + lane * 2);
    a.x += b.x; a.y += b.y;
    ((float2*)zout)[(size_t)warp * 32 + lane] = a;
    ((uint2*)zsp)[(size_t)warp * 32 + lane] = make_uint2(pack2(a.x), pack2(a.y));
}

// ===================== BatchNorm (stats fused into GEMM) =====================
__global__ void k_bn_finalize(const float* __restrict__ sum, const float* __restrict__ sumsq,
                              const float* __restrict__ gamma, const float* __restrict__ beta,
                              float* __restrict__ scale, float* __restrict__ shift) {
    int c = threadIdx.x;
    float invM = 1.f / (float)Nn;
    float m = sum[c] * invM;
    float v = fmaxf(sumsq[c] * invM - m * m, 0.f);
    float sc = gamma[c] * rsqrtf(v + EPSB);
    scale[c] = sc;
    shift[c] = beta[c] - m * sc;
}

// y = pack(relu(x*scale + shift))
__global__ void __launch_bounds__(256) k_bn_apply_pack(const float* __restrict__ x,
                                                       const float* __restrict__ scale,
                                                       const float* __restrict__ shift,
                                                       uint32_t* __restrict__ yp) {
    size_t idx = (size_t)blockIdx.x * blockDim.x + threadIdx.x;
    size_t n4 = (size_t)Nn * HC / 4;
    if (idx >= n4) return;
    int c = ((int)(idx & 63)) * 4;
    float4 v = ((const float4*)x)[idx];
    float4 sc = *(const float4*)(scale + c);
    float4 sh = *(const float4*)(shift + c);
    float t0 = fmaxf(fmaf(v.x, sc.x, sh.x), 0.f);
    float t1 = fmaxf(fmaf(v.y, sc.y, sh.y), 0.f);
    float t2 = fmaxf(fmaf(v.z, sc.z, sh.z), 0.f);
    float t3 = fmaxf(fmaf(v.w, sc.w, sh.w), 0.f);
    ((uint4*)yp)[idx] = make_uint4(pack2(t0), pack2(t1), pack2(t2), pack2(t3));
}

// ===================== mma.sync bf16 GEMM ====================================
// C[M,NT] = unpack(Ap)[M,KT] @ unpack(Bp)[NT,KT]^T (+bias)
// Compensated: Ahi*Bhi + Ahi*Blo + Alo*Bhi (fp32 accumulate).
// If STATS: per-column sum/sumsq of C accumulated into bnsum/bnsumsq (bias must be null).
__device__ __forceinline__ void mma16816(float* acc, const uint32_t* a, const uint32_t* b) {
    asm volatile(
        "mma.sync.aligned.m16n8k16.row.col.f32.bf16.bf16.f32 "
        "{%0,%1,%2,%3}, {%4,%5,%6,%7}, {%8,%9}, {%0,%1,%2,%3};"
        : "+f"(acc[0]), "+f"(acc[1]), "+f"(acc[2]), "+f"(acc[3])
        : "r"(a[0]), "r"(a[1]), "r"(a[2]), "r"(a[3]), "r"(b[0]), "r"(b[1]));
}

template <int KT, int NT, bool HAS_BIAS, bool STATS>
__global__ void __launch_bounds__(256) k_mma(const uint32_t* __restrict__ Ap,
                                             const uint32_t* __restrict__ Bp,
                                             const float* __restrict__ bias,
                                             float* __restrict__ C,
                                             float* __restrict__ bnsum,
                                             float* __restrict__ bnsumsq) {
    constexpr int M = Nn;
    __shared__ __nv_bfloat16 Ahi[128][40];
    __shared__ __nv_bfloat16 Alo[128][40];
    __shared__ __nv_bfloat16 Bhi[64][40];
    __shared__ __nv_bfloat16 Blo[64][40];

    int tid = threadIdx.x;
    int wid = tid >> 5, lane = tid & 31;
    int g = lane >> 2, tig = lane & 3;
    int warp_m = wid & 3, warp_n = wid >> 2;
    int bm = blockIdx.y * 128, bn = blockIdx.x * 64;

    float acc[2][4][4];
#pragma unroll
    for (int mt = 0; mt < 2; ++mt)
#pragma unroll
        for (int nt = 0; nt < 4; ++nt)
#pragma unroll
            for (int i = 0; i < 4; ++i) acc[mt][nt][i] = 0.f;

    for (int ch = 0; ch < KT / 32; ++ch) {
        const int k0 = ch * 32;
        // ---- stage A: 128 rows x 32 packed u32 -> Ahi/Alo
        {
            int r = tid >> 1;
            int koff = (tid & 1) * 16;
            bool valid = (bm + r) < M;
            uint4 v[4];
            if (valid) {
                const uint4* src = (const uint4*)(Ap + (size_t)(bm + r) * KT + k0 + koff);
#pragma unroll
                for (int q = 0; q < 4; ++q) v[q] = src[q];
            } else {
#pragma unroll
                for (int q = 0; q < 4; ++q) v[q] = make_uint4(0u, 0u, 0u, 0u);
            }
            const uint32_t* p = (const uint32_t*)v;
#pragma unroll
            for (int i = 0; i < 16; i += 2) {
                uint32_t p0 = p[i], p1 = p[i + 1];
                *(uint32_t*)&Ahi[r][koff + i] = (p0 & 0xFFFFu) | (p1 << 16);
                *(uint32_t*)&Alo[r][koff + i] = (p0 >> 16) | (p1 & 0xFFFF0000u);
            }
        }
        // ---- stage B: 64 rows x 32 packed u32 -> Bhi/Blo
        {
            int n = tid >> 2;
            int koff = (tid & 3) * 8;
            const uint4* src = (const uint4*)(Bp + (size_t)(bn + n) * KT + k0 + koff);
            uint4 v0 = src[0], v1 = src[1];
            uint32_t p[8] = {v0.x, v0.y, v0.z, v0.w, v1.x, v1.y, v1.z, v1.w};
#pragma unroll
            for (int i = 0; i < 8; i += 2) {
                uint32_t p0 = p[i], p1 = p[i + 1];
                *(uint32_t*)&Bhi[n][koff + i] = (p0 & 0xFFFFu) | (p1 << 16);
                *(uint32_t*)&Blo[n][koff + i] = (p0 >> 16) | (p1 & 0xFFFF0000u);
            }
        }
        __syncthreads();

#pragma unroll
        for (int kk = 0; kk < 32; kk += 16) {
            uint32_t ah[2][4], al[2][4], bh[4][2], bl[4][2];
            int cA = kk + tig * 2;
#pragma unroll
            for (int mt = 0; mt < 2; ++mt) {
                int r0 = warp_m * 32 + mt * 16 + g;
                ah[mt][0] = *(const uint32_t*)&Ahi[r0][cA];
                ah[mt][1] = *(const uint32_t*)&Ahi[r0 + 8][cA];
                ah[mt][2] = *(const uint32_t*)&Ahi[r0][cA + 8];
                ah[mt][3] = *(const uint32_t*)&Ahi[r0 + 8][cA + 8];
                al[mt][0] = *(const uint32_t*)&Alo[r0][cA];
                al[mt][1] = *(const uint32_t*)&Alo[r0 + 8][cA];
                al[mt][2] = *(const uint32_t*)&Alo[r0][cA + 8];
                al[mt][3] = *(const uint32_t*)&Alo[r0 + 8][cA + 8];
            }
#pragma unroll
            for (int nt = 0; nt < 4; ++nt) {
                int n0 = warp_n * 32 + nt * 8 + g;
                bh[nt][0] = *(const uint32_t*)&Bhi[n0][cA];
                bh[nt][1] = *(const uint32_t*)&Bhi[n0][cA + 8];
                bl[nt][0] = *(const uint32_t*)&Blo[n0][cA];
                bl[nt][1] = *(const uint32_t*)&Blo[n0][cA + 8];
            }
#pragma unroll
            for (int mt = 0; mt < 2; ++mt)
#pragma unroll
                for (int nt = 0; nt < 4; ++nt) {
                    mma16816(acc[mt][nt], ah[mt], bh[nt]);
                    mma16816(acc[mt][nt], ah[mt], bl[nt]);
                    mma16816(acc[mt][nt], al[mt], bh[nt]);
                }
        }
        __syncthreads();
    }

    // ---- epilogue: write C (+bias)
#pragma unroll
    for (int mt = 0; mt < 2; ++mt) {
        int r0 = bm + warp_m * 32 + mt * 16 + g;
#pragma unroll
        for (int nt = 0; nt < 4; ++nt) {
            int cc = bn + warp_n * 32 + nt * 8 + tig * 2;
            float b0 = 0.f, b1 = 0.f;
            if (HAS_BIAS) { b0 = bias[cc]; b1 = bias[cc + 1]; }
            if (r0 < M) {
                float2 v = make_float2(acc[mt][nt][0] + b0, acc[mt][nt][1] + b1);
                *(float2*)(C + (size_t)r0 * NT + cc) = v;
            }
            if (r0 + 8 < M) {
                float2 v = make_float2(acc[mt][nt][2] + b0, acc[mt][nt][3] + b1);
                *(float2*)(C + (size_t)(r0 + 8) * NT + cc) = v;
            }
        }
    }

    // ---- fused BN statistics (per-column sum / sumsq over this CTA's rows)
    if (STATS) {
#pragma unroll
        for (int nt = 0; nt < 4; ++nt) {
            float s0 = 0.f, s1 = 0.f, q0 = 0.f, q1 = 0.f;
#pragma unroll
            for (int mt = 0; mt < 2; ++mt) {
                int r0 = bm + warp_m * 32 + mt * 16 + g;
                if (r0 < M) {
                    float v0 = acc[mt][nt][0], v1 = acc[mt][nt][1];
                    s0 += v0; q0 += v0 * v0;
                    s1 += v1; q1 += v1 * v1;
                }
                if (r0 + 8 < M) {
                    float v0 = acc[mt][nt][2], v1 = acc[mt][nt][3];
                    s0 += v0; q0 += v0 * v0;
                    s1 += v1; q1 += v1 * v1;
                }
            }
            // reduce over the 8 g-lanes sharing this column pair (stride-4 lanes)
#pragma unroll
            for (int o = 4; o < 32; o <<= 1) {
                s0 += __shfl_xor_sync(0xFFFFFFFFu, s0, o);
                s1 += __shfl_xor_sync(0xFFFFFFFFu, s1, o);
                q0 += __shfl_xor_sync(0xFFFFFFFFu, q0, o);
                q1 += __shfl_xor_sync(0xFFFFFFFFu, q1, o);
            }
            if (lane < 4) {  // lane == tig, g == 0
                int cc = bn + warp_n * 32 + nt * 8 + lane * 2;
                atomicAdd(&bnsum[cc], s0);
                atomicAdd(&bnsum[cc + 1], s1);
                atomicAdd(&bnsumsq[cc], q0);
                atomicAdd(&bnsumsq[cc + 1], q1);
            }
        }
    }
}

// ===================== host orchestration ====================================
template <int KT, int NT, bool HAS_BIAS, bool STATS>
static void launch_mma(const uint32_t* Ap, const uint32_t* Bp, const float* bias,
                       float* C, float* bnsum, float* bnsumsq) {
    dim3 grid(NT / 64, (Nn + 127) / 128);
    k_mma<KT, NT, HAS_BIAS, STATS><<<grid, 256>>>(Ap, Bp, bias, C, bnsum, bnsumsq);
}

extern "C" void kernel_launch(void* const* d_in, const int* in_sizes, int n_in,
                              void* d_out, int out_size) {
    const float* x  = (const float*)d_in[0];
    const void*  ei = d_in[1];
    const float* W1 = (const float*)d_in[2];
    const float* g1 = (const float*)d_in[4];
    const float* be1 = (const float*)d_in[5];
    const float* W2 = (const float*)d_in[6];
    const float* g2 = (const float*)d_in[8];
    const float* be2 = (const float*)d_in[9];
    const float* W3 = (const float*)d_in[10];
    const float* b3 = (const float*)d_in[11];
    const float* dW1 = (const float*)d_in[12];
    const float* dg1 = (const float*)d_in[14];
    const float* dbe1 = (const float*)d_in[15];
    const float* dW2 = (const float*)d_in[16];
    const float* dg2 = (const float*)d_in[18];
    const float* dbe2 = (const float*)d_in[19];
    const float* dW3 = (const float*)d_in[20];
    const float* db3 = (const float*)d_in[21];

    float* out  = (float*)d_out;
    float* xhat = out;                           // [Nn, INC]
    float* zout = out + (size_t)Nn * INC;        // [Nn, LC]

    float *bufA, *zbuf, *dinv, *bnsum, *bnsumsq, *fscale, *fshift;
    uint32_t *P1, *P2, *zsp, *wsp;
    int *cnt, *rowstart, *wr, *colarr, *partial;
    cudaGetSymbolAddress((void**)&bufA, g_bufA);
    cudaGetSymbolAddress((void**)&P1, g_packP1);
    cudaGetSymbolAddress((void**)&P2, g_packP2);
    cudaGetSymbolAddress((void**)&zbuf, g_zbuf);
    cudaGetSymbolAddress((void**)&zsp, g_zsp);
    cudaGetSymbolAddress((void**)&wsp, g_wsplit);
    cudaGetSymbolAddress((void**)&dinv, g_dinv);
    cudaGetSymbolAddress((void**)&cnt, g_cnt);
    cudaGetSymbolAddress((void**)&rowstart, g_rowstart);
    cudaGetSymbolAddress((void**)&wr, g_wr);
    cudaGetSymbolAddress((void**)&colarr, g_col);
    cudaGetSymbolAddress((void**)&partial, g_partial);
    cudaGetSymbolAddress((void**)&bnsum, g_bnsum);
    cudaGetSymbolAddress((void**)&bnsumsq, g_bnsumsq);
    cudaGetSymbolAddress((void**)&fscale, g_scale);
    cudaGetSymbolAddress((void**)&fshift, g_shift);

    // ---- edge dtype detection + zero + CSR build (parallel scan) ----
    k_detect<<<1, 256>>>((const long long*)ei);
    k_zero_all<<<(Nn + 255) / 256, 256>>>(cnt, bnsum, bnsumsq);
    k_hist<<<(Ed + 255) / 256, 256>>>(ei, cnt);
    k_dinv<<<(Nn + 255) / 256, 256>>>(cnt, dinv);
    k_blocksum<<<SCAN_NB, 1024>>>(cnt, partial);
    k_scanpartial<<<1, 32>>>(partial, rowstart + Nn);
    k_scanlocal<<<SCAN_NB, 1024>>>(cnt, partial, rowstart, wr);
    k_scatter<<<(Ed + 255) / 256, 256>>>(ei, wr, colarr);

    // ---- weight transpose + split (tiny) ----
    k_wsplit<<<(INC * HC + 255) / 256, 256>>>(W1,  wsp + WOFF_1, INC, HC);
    k_wsplit<<<(HC * HC + 255) / 256, 256>>>(W2,  wsp + WOFF_2, HC, HC);
    k_wsplit<<<(HC * LC + 255) / 256, 256>>>(W3,  wsp + WOFF_3, HC, LC);
    k_wsplit<<<(LC * HC + 255) / 256, 256>>>(dW1, wsp + WOFF_4, LC, HC);
    k_wsplit<<<(HC * HC + 255) / 256, 256>>>(dW2, wsp + WOFF_5, HC, HC);
    k_wsplit<<<(HC * INC + 255) / 256, 256>>>(dW3, wsp + WOFF_6, HC, INC);

    const int aggBlocks = (Nn * 32 + 255) / 256;
    size_t n4 = (size_t)Nn * HC / 4;
    unsigned applyBlocks = (unsigned)((n4 + 255) / 256);

    // ---- encoder layer 1:  h1 = BNrelu( agg(x) @ W1 )  (agg/GEMM swapped) ----
    k_agg_f2p128<<<aggBlocks, 256>>>(x, rowstart, colarr, dinv, P2);
    launch_mma<INC, HC, false, true>(P2, wsp + WOFF_1, nullptr, bufA, bnsum, bnsumsq);
    k_bn_finalize<<<1, HC>>>(bnsum, bnsumsq, g1, be1, fscale, fshift);
    k_bn_apply_pack<<<applyBlocks, 256>>>(bufA, fscale, fshift, P1);

    // ---- encoder layer 2:  h2 = BNrelu( agg(h1) @ W2 ) ----
    k_agg_p2p256<<<aggBlocks, 256>>>(P1, rowstart, colarr, dinv, P2);
    launch_mma<HC, HC, false, true>(P2, wsp + WOFF_2, nullptr, bufA, bnsum + HC, bnsumsq + HC);
    k_bn_finalize<<<1, HC>>>(bnsum + HC, bnsumsq + HC, g2, be2, fscale, fshift);
    k_bn_apply_pack<<<applyBlocks, 256>>>(bufA, fscale, fshift, P1);

    // ---- encoder layer 3:  z = agg(h2 @ W3) + b3 ----
    launch_mma<HC, LC, false, false>(P1, wsp + WOFF_3, nullptr, zbuf, nullptr, nullptr);
    k_agg_z64<<<aggBlocks, 256>>>(zbuf, rowstart, colarr, dinv, b3, zout, zsp);

    // ---- decoder ----
    launch_mma<LC, HC, false, true>(zsp, wsp + WOFF_4, nullptr, bufA, bnsum + 2 * HC, bnsumsq + 2 * HC);
    k_bn_finalize<<<1, HC>>>(bnsum + 2 * HC, bnsumsq + 2 * HC, dg1, dbe1, fscale, fshift);
    k_bn_apply_pack<<<applyBlocks, 256>>>(bufA, fscale, fshift, P1);

    launch_mma<HC, HC, false, true>(P1, wsp + WOFF_5, nullptr, bufA, bnsum + 3 * HC, bnsumsq + 3 * HC);
    k_bn_finalize<<<1, HC>>>(bnsum + 3 * HC, bnsumsq + 3 * HC, dg2, dbe2, fscale, fshift);
    k_bn_apply_pack<<<applyBlocks, 256>>>(bufA, fscale, fshift, P2);

    launch_mma<HC, INC, true, false>(P2, wsp + WOFF_6, db3, xhat, nullptr, nullptr);
}

// round 8
// speedup vs baseline: 1.6041x; 1.0315x over previous
#include <cuda_runtime.h>
#include <cuda_bf16.h>
#include <cstdint>
#include <cstddef>

#define Nn   100000
#define Ed   1600000
#define INC  128
#define HC   256
#define LC   64
#define EPSB 1e-5f
#define SCAN_NB ((Nn + 1023) / 1024)   /* 98 */

// ===================== pack helper (weights only) ============================
__device__ __forceinline__ uint32_t pack2(float v) {
    __nv_bfloat16 h = __float2bfloat16(v);
    float hf = __bfloat162float(h);
    __nv_bfloat16 l = __float2bfloat16(v - hf);
    return (uint32_t)__bfloat16_as_ushort(h) | ((uint32_t)__bfloat16_as_ushort(l) << 16);
}

// ===================== scratch (device globals) ==============================
__device__ float    g_bufA[(size_t)Nn * HC];     // fp32 GEMM output
__device__ float    g_bufB[(size_t)Nn * HC];     // fp32 agg/BN staging
__device__ float    g_zbuf[(size_t)Nn * LC];
__device__ uint32_t g_wsplit[229376];            // all 6 weights, transposed+split
__device__ float    g_dinv[Nn];
__device__ int      g_cnt[Nn];
__device__ int      g_rowstart[Nn + 1];
__device__ int      g_wr[Nn];
__device__ int      g_col[Ed];
__device__ int      g_partial[SCAN_NB];
__device__ float    g_bnsum[4 * HC];             // 4 BN stat sets
__device__ float    g_bnsumsq[4 * HC];
__device__ float    g_scale[HC];
__device__ float    g_shift[HC];
__device__ int      g_is32;

// weight-split offsets within g_wsplit (u32 elems, layout [N][K])
#define WOFF_1 0        /* 256x128 */
#define WOFF_2 32768    /* 256x256 */
#define WOFF_3 98304    /* 64x256  */
#define WOFF_4 114688   /* 256x64  */
#define WOFF_5 131072   /* 256x256 */
#define WOFF_6 196608   /* 128x256 */

// ===================== edge dtype detection / CSR build ======================
__global__ void k_detect(const long long* __restrict__ ei64) {
    __shared__ int s_bad;
    if (threadIdx.x == 0) s_bad = 0;
    __syncthreads();
    long long v0 = ei64[threadIdx.x];
    long long v1 = ei64[(size_t)Ed + threadIdx.x];
    if (v0 < 0 || v0 >= (long long)Nn || v1 < 0 || v1 >= (long long)Nn) atomicOr(&s_bad, 1);
    __syncthreads();
    if (threadIdx.x == 0) g_is32 = s_bad ? 1 : 0;
}

__device__ __forceinline__ int edge_at(const void* ei, int is32, size_t pos) {
    if (is32) return ((const int*)ei)[pos];
    return (int)((const long long*)ei)[pos];
}

__global__ void k_zero_all(int* cnt, float* bnsum, float* bnsumsq) {
    int i = blockIdx.x * blockDim.x + threadIdx.x;
    if (i < Nn) cnt[i] = 0;
    if (i < 4 * HC) { bnsum[i] = 0.f; bnsumsq[i] = 0.f; }
}

__global__ void k_hist(const void* __restrict__ ei, int* __restrict__ cnt) {
    int e = blockIdx.x * blockDim.x + threadIdx.x;
    if (e >= Ed) return;
    int dst = edge_at(ei, g_is32, (size_t)Ed + e);
    if ((unsigned)dst < (unsigned)Nn) atomicAdd(&cnt[dst], 1);
}

__global__ void k_dinv(const int* __restrict__ cnt, float* __restrict__ dinv) {
    int i = blockIdx.x * blockDim.x + threadIdx.x;
    if (i < Nn) dinv[i] = rsqrtf((float)(cnt[i] + 1));
}

// ---- parallel 3-phase exclusive scan ----------------------------------------
__global__ void __launch_bounds__(1024) k_blocksum(const int* __restrict__ cnt,
                                                   int* __restrict__ partial) {
    int i = blockIdx.x * 1024 + threadIdx.x;
    int v = (i < Nn) ? cnt[i] : 0;
    for (int o = 16; o; o >>= 1) v += __shfl_down_sync(0xFFFFFFFFu, v, o);
    __shared__ int ws[32];
    if ((threadIdx.x & 31) == 0) ws[threadIdx.x >> 5] = v;
    __syncthreads();
    if (threadIdx.x < 32) {
        int t = ws[threadIdx.x];
        for (int o = 16; o; o >>= 1) t += __shfl_down_sync(0xFFFFFFFFu, t, o);
        if (threadIdx.x == 0) partial[blockIdx.x] = t;
    }
}

__global__ void k_scanpartial(int* __restrict__ partial, int* __restrict__ rowlast) {
    if (threadIdx.x == 0) {
        int run = 0;
        for (int b = 0; b < SCAN_NB; ++b) {
            int t = partial[b];
            partial[b] = run;
            run += t;
        }
        rowlast[0] = (run <= Ed) ? run : Ed;
    }
}

__global__ void __launch_bounds__(1024) k_scanlocal(const int* __restrict__ cnt,
                                                    const int* __restrict__ partial,
                                                    int* __restrict__ rowstart,
                                                    int* __restrict__ wr) {
    int i = blockIdx.x * 1024 + threadIdx.x;
    int v = (i < Nn) ? cnt[i] : 0;
    int lane = threadIdx.x & 31, w = threadIdx.x >> 5;
    int incl = v;
    for (int o = 1; o < 32; o <<= 1) {
        int t = __shfl_up_sync(0xFFFFFFFFu, incl, o);
        if (lane >= o) incl += t;
    }
    __shared__ int ws[32];
    if (lane == 31) ws[w] = incl;
    __syncthreads();
    if (threadIdx.x < 32) {
        int t = ws[threadIdx.x];
        int sc = t;
        for (int o = 1; o < 32; o <<= 1) {
            int u = __shfl_up_sync(0xFFFFFFFFu, sc, o);
            if (threadIdx.x >= o) sc += u;
        }
        ws[threadIdx.x] = sc - t;   // exclusive warp offset
    }
    __syncthreads();
    int excl = incl - v + ws[w] + partial[blockIdx.x];
    if (i < Nn) { rowstart[i] = excl; wr[i] = excl; }
}

__global__ void k_scatter(const void* __restrict__ ei,
                          int* __restrict__ wr, int* __restrict__ col) {
    int e = blockIdx.x * blockDim.x + threadIdx.x;
    if (e >= Ed) return;
    int is32 = g_is32;
    int src = edge_at(ei, is32, (size_t)e);
    int dst = edge_at(ei, is32, (size_t)Ed + e);
    if ((unsigned)dst >= (unsigned)Nn || (unsigned)src >= (unsigned)Nn) return;
    int pos = atomicAdd(&wr[dst], 1);
    if ((unsigned)pos < (unsigned)Ed) col[pos] = src;
}

// ===================== weight transpose + split ==============================
__global__ void k_wsplit(const float* __restrict__ W, uint32_t* __restrict__ out, int K, int N) {
    int idx = blockIdx.x * blockDim.x + threadIdx.x;
    if (idx >= K * N) return;
    int k = idx / N, n = idx % N;
    out[(size_t)n * K + k] = pack2(W[idx]);
}

// ===================== aggregations (one warp per node, all fp32) ============
// out[i] = dinv[i]^2 * h[i] + sum_j dinv[i]*dinv[s_j]*h[s_j]
__global__ void __launch_bounds__(256) k_agg128(const float* __restrict__ h,
                                                const int* __restrict__ rowstart,
                                                const int* __restrict__ col,
                                                const float* __restrict__ dinv,
                                                float* __restrict__ outp) {
    int warp = (blockIdx.x * blockDim.x + threadIdx.x) >> 5;
    int lane = threadIdx.x & 31;
    if (warp >= Nn) return;
    float di = dinv[warp];
    int jb = rowstart[warp], je = rowstart[warp + 1];
    const float4* h4 = (const float4*)h;  // 32 float4 per row
    float cs = di * di;
    float4 x = h4[(size_t)warp * 32 + lane];
    float4 a = make_float4(cs * x.x, cs * x.y, cs * x.z, cs * x.w);
    for (int j = jb; j < je; ++j) {
        int s = col[j];
        float c = di * dinv[s];
        float4 y = h4[(size_t)s * 32 + lane];
        a.x += c * y.x; a.y += c * y.y; a.z += c * y.z; a.w += c * y.w;
    }
    ((float4*)outp)[(size_t)warp * 32 + lane] = a;
}

// agg over BN(relu(raw)) rows, width 256: applies scale/shift/relu inline
__global__ void __launch_bounds__(256) k_agg256_bn(const float* __restrict__ h,
                                                   const int* __restrict__ rowstart,
                                                   const int* __restrict__ col,
                                                   const float* __restrict__ dinv,
                                                   const float* __restrict__ scale,
                                                   const float* __restrict__ shift,
                                                   float* __restrict__ outp) {
    int warp = (blockIdx.x * blockDim.x + threadIdx.x) >> 5;
    int lane = threadIdx.x & 31;
    if (warp >= Nn) return;
    float di = dinv[warp];
    int jb = rowstart[warp], je = rowstart[warp + 1];
    const float4* h4 = (const float4*)h;  // 64 float4 per row
    int f0 = lane, f1 = lane + 32;
    float4 sc0 = ((const float4*)scale)[f0], sh0 = ((const float4*)shift)[f0];
    float4 sc1 = ((const float4*)scale)[f1], sh1 = ((const float4*)shift)[f1];
    float cs = di * di;
    float4 a0, a1;
    {
        float4 x0 = h4[(size_t)warp * 64 + f0];
        float4 x1 = h4[(size_t)warp * 64 + f1];
        a0.x = cs * fmaxf(fmaf(x0.x, sc0.x, sh0.x), 0.f);
        a0.y = cs * fmaxf(fmaf(x0.y, sc0.y, sh0.y), 0.f);
        a0.z = cs * fmaxf(fmaf(x0.z, sc0.z, sh0.z), 0.f);
        a0.w = cs * fmaxf(fmaf(x0.w, sc0.w, sh0.w), 0.f);
        a1.x = cs * fmaxf(fmaf(x1.x, sc1.x, sh1.x), 0.f);
        a1.y = cs * fmaxf(fmaf(x1.y, sc1.y, sh1.y), 0.f);
        a1.z = cs * fmaxf(fmaf(x1.z, sc1.z, sh1.z), 0.f);
        a1.w = cs * fmaxf(fmaf(x1.w, sc1.w, sh1.w), 0.f);
    }
    for (int j = jb; j < je; ++j) {
        int s = col[j];
        float c = di * dinv[s];
        float4 y0 = h4[(size_t)s * 64 + f0];
        float4 y1 = h4[(size_t)s * 64 + f1];
        a0.x += c * fmaxf(fmaf(y0.x, sc0.x, sh0.x), 0.f);
        a0.y += c * fmaxf(fmaf(y0.y, sc0.y, sh0.y), 0.f);
        a0.z += c * fmaxf(fmaf(y0.z, sc0.z, sh0.z), 0.f);
        a0.w += c * fmaxf(fmaf(y0.w, sc0.w, sh0.w), 0.f);
        a1.x += c * fmaxf(fmaf(y1.x, sc1.x, sh1.x), 0.f);
        a1.y += c * fmaxf(fmaf(y1.y, sc1.y, sh1.y), 0.f);
        a1.z += c * fmaxf(fmaf(y1.z, sc1.z, sh1.z), 0.f);
        a1.w += c * fmaxf(fmaf(y1.w, sc1.w, sh1.w), 0.f);
    }
    ((float4*)outp)[(size_t)warp * 64 + f0] = a0;
    ((float4*)outp)[(size_t)warp * 64 + f1] = a1;
}

__global__ void __launch_bounds__(256) k_agg_z64(const float* __restrict__ h,
                                                 const int* __restrict__ rowstart,
                                                 const int* __restrict__ col,
                                                 const float* __restrict__ dinv,
                                                 const float* __restrict__ bias,
                                                 float* __restrict__ zout) {
    int warp = (blockIdx.x * blockDim.x + threadIdx.x) >> 5;
    int lane = threadIdx.x & 31;
    if (warp >= Nn) return;
    float di = dinv[warp];
    int jb = rowstart[warp], je = rowstart[warp + 1];
    const float2* h2 = (const float2*)h;  // 32 float2 per row
    float cs = di * di;
    float2 x = h2[(size_t)warp * 32 + lane];
    float2 a = make_float2(cs * x.x, cs * x.y);
    for (int j = jb; j < je; ++j) {
        int s = col[j];
        float c = di * dinv[s];
        float2 y = h2[(size_t)s * 32 + lane];
        a.x += c * y.x; a.y += c * y.y;
    }
    float2 b = *(const float2*)(bias + lane * 2);
    a.x += b.x; a.y += b.y;
    ((float2*)zout)[(size_t)warp * 32 + lane] = a;
}

// ===================== BatchNorm finalize (stats fused into GEMM) ============
__global__ void k_bn_finalize(const float* __restrict__ sum, const float* __restrict__ sumsq,
                              const float* __restrict__ gamma, const float* __restrict__ beta,
                              float* __restrict__ scale, float* __restrict__ shift) {
    int c = threadIdx.x;
    float invM = 1.f / (float)Nn;
    float m = sum[c] * invM;
    float v = fmaxf(sumsq[c] * invM - m * m, 0.f);
    float sc = gamma[c] * rsqrtf(v + EPSB);
    scale[c] = sc;
    shift[c] = beta[c] - m * sc;
}

// ===================== mma.sync bf16 GEMM ====================================
// C[M,NT] = split(bnA?(A))[M,KT] @ unpack(Bp)[NT,KT]^T (+bias)
// A: fp32 rows; hi/lo bf16 split happens during smem staging.
// BNA: apply relu(a*scaleA+shiftA) during staging (per-K-column params).
// STATS: per-column sum/sumsq of C accumulated into bnsum/bnsumsq.
__device__ __forceinline__ void mma16816(float* acc, const uint32_t* a, const uint32_t* b) {
    asm volatile(
        "mma.sync.aligned.m16n8k16.row.col.f32.bf16.bf16.f32 "
        "{%0,%1,%2,%3}, {%4,%5,%6,%7}, {%8,%9}, {%0,%1,%2,%3};"
        : "+f"(acc[0]), "+f"(acc[1]), "+f"(acc[2]), "+f"(acc[3])
        : "r"(a[0]), "r"(a[1]), "r"(a[2]), "r"(a[3]), "r"(b[0]), "r"(b[1]));
}

template <int KT, int NT, bool HAS_BIAS, bool STATS, bool BNA>
__global__ void __launch_bounds__(256) k_mma(const float* __restrict__ A,
                                             const uint32_t* __restrict__ Bp,
                                             const float* __restrict__ bias,
                                             float* __restrict__ C,
                                             float* __restrict__ bnsum,
                                             float* __restrict__ bnsumsq,
                                             const float* __restrict__ scaleA,
                                             const float* __restrict__ shiftA) {
    constexpr int M = Nn;
    __shared__ __nv_bfloat16 Ahi[128][40];
    __shared__ __nv_bfloat16 Alo[128][40];
    __shared__ __nv_bfloat16 Bhi[64][40];
    __shared__ __nv_bfloat16 Blo[64][40];

    int tid = threadIdx.x;
    int wid = tid >> 5, lane = tid & 31;
    int g = lane >> 2, tig = lane & 3;
    int warp_m = wid & 3, warp_n = wid >> 2;
    int bm = blockIdx.y * 128, bn = blockIdx.x * 64;

    float acc[2][4][4];
#pragma unroll
    for (int mt = 0; mt < 2; ++mt)
#pragma unroll
        for (int nt = 0; nt < 4; ++nt)
#pragma unroll
            for (int i = 0; i < 4; ++i) acc[mt][nt][i] = 0.f;

    for (int ch = 0; ch < KT / 32; ++ch) {
        const int k0 = ch * 32;
        // ---- stage A: 128 rows x 32 fp32 -> BN? -> Ahi/Alo bf16 split
        {
            int r = tid >> 1;
            int koff = (tid & 1) * 16;
            bool valid = (bm + r) < M;
            float v[16];
            if (valid) {
                const float4* src = (const float4*)(A + (size_t)(bm + r) * KT + k0 + koff);
#pragma unroll
                for (int q = 0; q < 4; ++q) *(float4*)&v[q * 4] = src[q];
            } else {
#pragma unroll
                for (int q = 0; q < 16; ++q) v[q] = 0.f;
            }
            if (BNA) {
                const float4* scp = (const float4*)(scaleA + k0 + koff);
                const float4* shp = (const float4*)(shiftA + k0 + koff);
#pragma unroll
                for (int q = 0; q < 4; ++q) {
                    float4 sc = scp[q], sh = shp[q];
                    v[q * 4 + 0] = fmaxf(fmaf(v[q * 4 + 0], sc.x, sh.x), 0.f);
                    v[q * 4 + 1] = fmaxf(fmaf(v[q * 4 + 1], sc.y, sh.y), 0.f);
                    v[q * 4 + 2] = fmaxf(fmaf(v[q * 4 + 2], sc.z, sh.z), 0.f);
                    v[q * 4 + 3] = fmaxf(fmaf(v[q * 4 + 3], sc.w, sh.w), 0.f);
                }
            }
#pragma unroll
            for (int i = 0; i < 16; i += 2) {
                __nv_bfloat16 h0 = __float2bfloat16(v[i]);
                __nv_bfloat16 h1 = __float2bfloat16(v[i + 1]);
                __nv_bfloat16 l0 = __float2bfloat16(v[i] - __bfloat162float(h0));
                __nv_bfloat16 l1 = __float2bfloat16(v[i + 1] - __bfloat162float(h1));
                *(uint32_t*)&Ahi[r][koff + i] =
                    (uint32_t)__bfloat16_as_ushort(h0) | ((uint32_t)__bfloat16_as_ushort(h1) << 16);
                *(uint32_t*)&Alo[r][koff + i] =
                    (uint32_t)__bfloat16_as_ushort(l0) | ((uint32_t)__bfloat16_as_ushort(l1) << 16);
            }
        }
        // ---- stage B: 64 rows x 32 packed u32 -> Bhi/Blo
        {
            int n = tid >> 2;
            int koff = (tid & 3) * 8;
            const uint4* src = (const uint4*)(Bp + (size_t)(bn + n) * KT + k0 + koff);
            uint4 v0 = src[0], v1 = src[1];
            uint32_t p[8] = {v0.x, v0.y, v0.z, v0.w, v1.x, v1.y, v1.z, v1.w};
#pragma unroll
            for (int i = 0; i < 8; i += 2) {
                uint32_t p0 = p[i], p1 = p[i + 1];
                *(uint32_t*)&Bhi[n][koff + i] = (p0 & 0xFFFFu) | (p1 << 16);
                *(uint32_t*)&Blo[n][koff + i] = (p0 >> 16) | (p1 & 0xFFFF0000u);
            }
        }
        __syncthreads();

#pragma unroll
        for (int kk = 0; kk < 32; kk += 16) {
            uint32_t ah[2][4], al[2][4], bh[4][2], bl[4][2];
            int cA = kk + tig * 2;
#pragma unroll
            for (int mt = 0; mt < 2; ++mt) {
                int r0 = warp_m * 32 + mt * 16 + g;
                ah[mt][0] = *(const uint32_t*)&Ahi[r0][cA];
                ah[mt][1] = *(const uint32_t*)&Ahi[r0 + 8][cA];
                ah[mt][2] = *(const uint32_t*)&Ahi[r0][cA + 8];
                ah[mt][3] = *(const uint32_t*)&Ahi[r0 + 8][cA + 8];
                al[mt][0] = *(const uint32_t*)&Alo[r0][cA];
                al[mt][1] = *(const uint32_t*)&Alo[r0 + 8][cA];
                al[mt][2] = *(const uint32_t*)&Alo[r0][cA + 8];
                al[mt][3] = *(const uint32_t*)&Alo[r0 + 8][cA + 8];
            }
#pragma unroll
            for (int nt = 0; nt < 4; ++nt) {
                int n0 = warp_n * 32 + nt * 8 + g;
                bh[nt][0] = *(const uint32_t*)&Bhi[n0][cA];
                bh[nt][1] = *(const uint32_t*)&Bhi[n0][cA + 8];
                bl[nt][0] = *(const uint32_t*)&Blo[n0][cA];
                bl[nt][1] = *(const uint32_t*)&Blo[n0][cA + 8];
            }
#pragma unroll
            for (int mt = 0; mt < 2; ++mt)
#pragma unroll
                for (int nt = 0; nt < 4; ++nt) {
                    mma16816(acc[mt][nt], ah[mt], bh[nt]);
                    mma16816(acc[mt][nt], ah[mt], bl[nt]);
                    mma16816(acc[mt][nt], al[mt], bh[nt]);
                }
        }
        __syncthreads();
    }

    // ---- epilogue: write C (+bias)
#pragma unroll
    for (int mt = 0; mt < 2; ++mt) {
        int r0 = bm + warp_m * 32 + mt * 16 + g;
#pragma unroll
        for (int nt = 0; nt < 4; ++nt) {
            int cc = bn + warp_n * 32 + nt * 8 + tig * 2;
            float b0 = 0.f, b1 = 0.f;
            if (HAS_BIAS) { b0 = bias[cc]; b1 = bias[cc + 1]; }
            if (r0 < M) {
                float2 v = make_float2(acc[mt][nt][0] + b0, acc[mt][nt][1] + b1);
                *(float2*)(C + (size_t)r0 * NT + cc) = v;
            }
            if (r0 + 8 < M) {
                float2 v = make_float2(acc[mt][nt][2] + b0, acc[mt][nt][3] + b1);
                *(float2*)(C + (size_t)(r0 + 8) * NT + cc) = v;
            }
        }
    }

    // ---- fused BN statistics (per-column sum / sumsq over this CTA's rows)
    if (STATS) {
#pragma unroll
        for (int nt = 0; nt < 4; ++nt) {
            float s0 = 0.f, s1 = 0.f, q0 = 0.f, q1 = 0.f;
#pragma unroll
            for (int mt = 0; mt < 2; ++mt) {
                int r0 = bm + warp_m * 32 + mt * 16 + g;
                if (r0 < M) {
                    float v0 = acc[mt][nt][0], v1 = acc[mt][nt][1];
                    s0 += v0; q0 += v0 * v0;
                    s1 += v1; q1 += v1 * v1;
                }
                if (r0 + 8 < M) {
                    float v0 = acc[mt][nt][2], v1 = acc[mt][nt][3];
                    s0 += v0; q0 += v0 * v0;
                    s1 += v1; q1 += v1 * v1;
                }
            }
#pragma unroll
            for (int o = 4; o < 32; o <<= 1) {
                s0 += __shfl_xor_sync(0xFFFFFFFFu, s0, o);
                s1 += __shfl_xor_sync(0xFFFFFFFFu, s1, o);
                q0 += __shfl_xor_sync(0xFFFFFFFFu, q0, o);
                q1 += __shfl_xor_sync(0xFFFFFFFFu, q1, o);
            }
            if (lane < 4) {  // lane == tig, g == 0
                int cc = bn + warp_n * 32 + nt * 8 + lane * 2;
                atomicAdd(&bnsum[cc], s0);
                atomicAdd(&bnsum[cc + 1], s1);
                atomicAdd(&bnsumsq[cc], q0);
                atomicAdd(&bnsumsq[cc + 1], q1);
            }
        }
    }
}

// ===================== host orchestration ====================================
template <int KT, int NT, bool HAS_BIAS, bool STATS, bool BNA>
static void launch_mma(const float* A, const uint32_t* Bp, const float* bias,
                       float* C, float* bnsum, float* bnsumsq,
                       const float* scaleA, const float* shiftA) {
    dim3 grid(NT / 64, (Nn + 127) / 128);
    k_mma<KT, NT, HAS_BIAS, STATS, BNA><<<grid, 256>>>(A, Bp, bias, C, bnsum, bnsumsq,
                                                       scaleA, shiftA);
}

extern "C" void kernel_launch(void* const* d_in, const int* in_sizes, int n_in,
                              void* d_out, int out_size) {
    const float* x  = (const float*)d_in[0];
    const void*  ei = d_in[1];
    const float* W1 = (const float*)d_in[2];
    const float* g1 = (const float*)d_in[4];
    const float* be1 = (const float*)d_in[5];
    const float* W2 = (const float*)d_in[6];
    const float* g2 = (const float*)d_in[8];
    const float* be2 = (const float*)d_in[9];
    const float* W3 = (const float*)d_in[10];
    const float* b3 = (const float*)d_in[11];
    const float* dW1 = (const float*)d_in[12];
    const float* dg1 = (const float*)d_in[14];
    const float* dbe1 = (const float*)d_in[15];
    const float* dW2 = (const float*)d_in[16];
    const float* dg2 = (const float*)d_in[18];
    const float* dbe2 = (const float*)d_in[19];
    const float* dW3 = (const float*)d_in[20];
    const float* db3 = (const float*)d_in[21];

    float* out  = (float*)d_out;
    float* xhat = out;                           // [Nn, INC]
    float* zout = out + (size_t)Nn * INC;        // [Nn, LC]

    float *bufA, *bufB, *zbuf, *dinv, *bnsum, *bnsumsq, *fscale, *fshift;
    uint32_t *wsp;
    int *cnt, *rowstart, *wr, *colarr, *partial;
    cudaGetSymbolAddress((void**)&bufA, g_bufA);
    cudaGetSymbolAddress((void**)&bufB, g_bufB);
    cudaGetSymbolAddress((void**)&zbuf, g_zbuf);
    cudaGetSymbolAddress((void**)&wsp, g_wsplit);
    cudaGetSymbolAddress((void**)&dinv, g_dinv);
    cudaGetSymbolAddress((void**)&cnt, g_cnt);
    cudaGetSymbolAddress((void**)&rowstart, g_rowstart);
    cudaGetSymbolAddress((void**)&wr, g_wr);
    cudaGetSymbolAddress((void**)&colarr, g_col);
    cudaGetSymbolAddress((void**)&partial, g_partial);
    cudaGetSymbolAddress((void**)&bnsum, g_bnsum);
    cudaGetSymbolAddress((void**)&bnsumsq, g_bnsumsq);
    cudaGetSymbolAddress((void**)&fscale, g_scale);
    cudaGetSymbolAddress((void**)&fshift, g_shift);

    // ---- edge dtype detection + zero + CSR build (parallel scan) ----
    k_detect<<<1, 256>>>((const long long*)ei);
    k_zero_all<<<(Nn + 255) / 256, 256>>>(cnt, bnsum, bnsumsq);
    k_hist<<<(Ed + 255) / 256, 256>>>(ei, cnt);
    k_dinv<<<(Nn + 255) / 256, 256>>>(cnt, dinv);
    k_blocksum<<<SCAN_NB, 1024>>>(cnt, partial);
    k_scanpartial<<<1, 32>>>(partial, rowstart + Nn);
    k_scanlocal<<<SCAN_NB, 1024>>>(cnt, partial, rowstart, wr);
    k_scatter<<<(Ed + 255) / 256, 256>>>(ei, wr, colarr);

    // ---- weight transpose + split (tiny) ----
    k_wsplit<<<(INC * HC + 255) / 256, 256>>>(W1,  wsp + WOFF_1, INC, HC);
    k_wsplit<<<(HC * HC + 255) / 256, 256>>>(W2,  wsp + WOFF_2, HC, HC);
    k_wsplit<<<(HC * LC + 255) / 256, 256>>>(W3,  wsp + WOFF_3, HC, LC);
    k_wsplit<<<(LC * HC + 255) / 256, 256>>>(dW1, wsp + WOFF_4, LC, HC);
    k_wsplit<<<(HC * HC + 255) / 256, 256>>>(dW2, wsp + WOFF_5, HC, HC);
    k_wsplit<<<(HC * INC + 255) / 256, 256>>>(dW3, wsp + WOFF_6, HC, INC);

    const int aggBlocks = (Nn * 32 + 255) / 256;

    // ---- encoder layer 1:  raw1 = agg(x) @ W1 ; stats0 ----
    k_agg128<<<aggBlocks, 256>>>(x, rowstart, colarr, dinv, bufB);
    launch_mma<INC, HC, false, true, false>(bufB, wsp + WOFF_1, nullptr, bufA,
                                            bnsum, bnsumsq, nullptr, nullptr);
    k_bn_finalize<<<1, HC>>>(bnsum, bnsumsq, g1, be1, fscale, fshift);

    // ---- encoder layer 2:  raw2 = agg(BNrelu(raw1)) @ W2 ; stats1 ----
    k_agg256_bn<<<aggBlocks, 256>>>(bufA, rowstart, colarr, dinv, fscale, fshift, bufB);
    launch_mma<HC, HC, false, true, false>(bufB, wsp + WOFF_2, nullptr, bufA,
                                           bnsum + HC, bnsumsq + HC, nullptr, nullptr);
    k_bn_finalize<<<1, HC>>>(bnsum + HC, bnsumsq + HC, g2, be2, fscale, fshift);

    // ---- encoder layer 3:  z = agg( BNrelu(raw2) @ W3 ) + b3 ----
    launch_mma<HC, LC, false, false, true>(bufA, wsp + WOFF_3, nullptr, zbuf,
                                           nullptr, nullptr, fscale, fshift);
    k_agg_z64<<<aggBlocks, 256>>>(zbuf, rowstart, colarr, dinv, b3, zout);

    // ---- decoder ----
    launch_mma<LC, HC, false, true, false>(zout, wsp + WOFF_4, nullptr, bufA,
                                           bnsum + 2 * HC, bnsumsq + 2 * HC, nullptr, nullptr);
    k_bn_finalize<<<1, HC>>>(bnsum + 2 * HC, bnsumsq + 2 * HC, dg1, dbe1, fscale, fshift);

    launch_mma<HC, HC, false, true, true>(bufA, wsp + WOFF_5, nullptr, bufB,
                                          bnsum + 3 * HC, bnsumsq + 3 * HC, fscale, fshift);
    k_bn_finalize<<<1, HC>>>(bnsum + 3 * HC, bnsumsq + 3 * HC, dg2, dbe2, fscale, fshift);

    launch_mma<HC, INC, true, false, true>(bufB, wsp + WOFF_6, db3, xhat,
                                           nullptr, nullptr, fscale, fshift);
}